// round 1
// baseline (speedup 1.0000x reference)
#include <cuda_runtime.h>

#define N_NODES 100000
#define N_EDGES 1600000
#define DIM     128
#define NCLS    64

// ---------------- scratch (device globals; no allocation in kernel_launch) ---
__device__ int   g_deg[N_NODES];
__device__ int   g_off[N_NODES + 1];
__device__ int   g_cur[N_NODES];
__device__ int   g_csr[N_EDGES];
__device__ float g_invdeg[N_NODES];
__device__ float g_agg[(long long)N_NODES * DIM];
__device__ float g_h1 [(long long)N_NODES * DIM];
__device__ float g_h2 [(long long)N_NODES * DIM];

// ---------------- packed f32x2 helpers --------------------------------------
#define FMA2(d, a, b, c) \
    asm("fma.rn.f32x2 %0, %1, %2, %3;" : "=l"(d) : "l"(a), "l"(b), "l"(c))
#define PACK2(d, x) \
    asm("mov.b64 %0, {%1, %2};" : "=l"(d) : "f"(x), "f"(x))
#define UNPACK2(lo, hi, v) \
    asm("mov.b64 {%0, %1}, %2;" : "=f"(lo), "=f"(hi) : "l"(v))

// ---------------- CSR build --------------------------------------------------
__global__ void zero_deg_kernel() {
    int i = blockIdx.x * blockDim.x + threadIdx.x;
    if (i < N_NODES) g_deg[i] = 0;
}

__global__ void count_deg_kernel(const int* __restrict__ dst) {
    int i = blockIdx.x * blockDim.x + threadIdx.x;
    if (i < N_EDGES) atomicAdd(&g_deg[dst[i]], 1);
}

// Single-block scan over 100k degrees: offsets, cursors, 1/max(deg,1).
__global__ void scan_invdeg_kernel() {
    __shared__ int sh[1024];
    const int t  = threadIdx.x;
    const int CH = (N_NODES + 1023) >> 10;   // 98
    int b = t * CH;
    int e = b + CH; if (e > N_NODES) e = N_NODES;
    int s = 0;
    for (int i = b; i < e; i++) s += g_deg[i];
    sh[t] = s;
    __syncthreads();
    // Hillis-Steele inclusive scan
    for (int d = 1; d < 1024; d <<= 1) {
        int v = (t >= d) ? sh[t - d] : 0;
        __syncthreads();
        sh[t] += v;
        __syncthreads();
    }
    int off = sh[t] - s;                      // exclusive prefix
    for (int i = b; i < e; i++) {
        int dg = g_deg[i];
        g_off[i] = off;
        g_cur[i] = off;
        g_invdeg[i] = 1.0f / (float)(dg > 0 ? dg : 1);
        off += dg;
    }
    if (t == 1023) g_off[N_NODES] = off;
}

__global__ void build_csr_kernel(const int* __restrict__ src,
                                 const int* __restrict__ dst) {
    int i = blockIdx.x * blockDim.x + threadIdx.x;
    if (i < N_EDGES) {
        int d = dst[i];
        int p = atomicAdd(&g_cur[d], 1);
        g_csr[p] = src[i];
    }
}

// ---------------- gather-side mean aggregation (warp per node) ---------------
__global__ void gather_mean_kernel(const float* __restrict__ h,
                                   float* __restrict__ out) {
    int warp = (blockIdx.x * blockDim.x + threadIdx.x) >> 5;
    if (warp >= N_NODES) return;
    int lane = threadIdx.x & 31;

    int s0 = g_off[warp];
    int s1 = g_off[warp + 1];

    float4 acc = make_float4(0.f, 0.f, 0.f, 0.f);

    for (int e = s0; e < s1; e += 32) {
        int idx = (e + lane < s1) ? g_csr[e + lane] : 0;
        int cnt = s1 - e; if (cnt > 32) cnt = 32;
        int j = 0;
        // batch 4 independent row loads for MLP
        for (; j + 4 <= cnt; j += 4) {
            int i0 = __shfl_sync(0xffffffffu, idx, j + 0);
            int i1 = __shfl_sync(0xffffffffu, idx, j + 1);
            int i2 = __shfl_sync(0xffffffffu, idx, j + 2);
            int i3 = __shfl_sync(0xffffffffu, idx, j + 3);
            float4 v0 = *(const float4*)(h + (long long)i0 * DIM + lane * 4);
            float4 v1 = *(const float4*)(h + (long long)i1 * DIM + lane * 4);
            float4 v2 = *(const float4*)(h + (long long)i2 * DIM + lane * 4);
            float4 v3 = *(const float4*)(h + (long long)i3 * DIM + lane * 4);
            acc.x += v0.x; acc.y += v0.y; acc.z += v0.z; acc.w += v0.w;
            acc.x += v1.x; acc.y += v1.y; acc.z += v1.z; acc.w += v1.w;
            acc.x += v2.x; acc.y += v2.y; acc.z += v2.z; acc.w += v2.w;
            acc.x += v3.x; acc.y += v3.y; acc.z += v3.z; acc.w += v3.w;
        }
        for (; j < cnt; j++) {
            int s = __shfl_sync(0xffffffffu, idx, j);
            float4 v = *(const float4*)(h + (long long)s * DIM + lane * 4);
            acc.x += v.x; acc.y += v.y; acc.z += v.z; acc.w += v.w;
        }
    }

    float inv = g_invdeg[warp];
    float4 r = make_float4(acc.x * inv, acc.y * inv, acc.z * inv, acc.w * inv);
    *(float4*)(out + (long long)warp * DIM + lane * 4) = r;
}

// ---------------- fused GEMM:  out = act(A1@W1 [+ A2@W2] + b) ---------------
// Tile: 128 rows x NC cols per 256-thread CTA. Row-pair packed f32x2 FMAs.
template <int KTOT, int NC, bool RELU, bool DUAL>
__global__ void __launch_bounds__(256, 1)
gemm_kernel(const float* __restrict__ A1, const float* __restrict__ A2,
            const float* __restrict__ W1, const float* __restrict__ W2,
            const float* __restrict__ bias,
            float* __restrict__ out, int M) {
    constexpr int COLG = NC / 8;        // threads across cols (8 cols each)
    constexpr int ROWG = 256 / COLG;    // thread groups across rows
    constexpr int RPT  = 128 / ROWG;    // rows per thread (even)
    constexpr int NP   = RPT / 2;       // row pairs per thread
    constexpr int KC   = 16;            // k chunk
    constexpr int AST  = 130;           // padded A smem stride

    extern __shared__ float smem[];
    float* Ws = smem;                   // [KTOT][NC]
    float* As = smem + KTOT * NC;       // [KC][AST]

    const int t  = threadIdx.x;
    const int cg = t % COLG;
    const int rg = t / COLG;
    const int c0 = cg * 8;
    const int r0 = rg * RPT;
    const int row0 = blockIdx.x * 128;

    // --- weights into smem (K-major rows are contiguous) ---
    {
        const float4* w1 = (const float4*)W1;
        for (int f = t; f < (128 * NC) / 4; f += 256)
            ((float4*)Ws)[f] = w1[f];
        if (DUAL) {
            const float4* w2 = (const float4*)W2;
            for (int f = t; f < (128 * NC) / 4; f += 256)
                ((float4*)Ws)[(128 * NC) / 4 + f] = w2[f];
        }
    }

    float bs[8];
#pragma unroll
    for (int j = 0; j < 8; j++) bs[j] = bias[c0 + j];

    unsigned long long acc[NP][8];
#pragma unroll
    for (int p = 0; p < NP; p++)
#pragma unroll
        for (int j = 0; j < 8; j++) acc[p][j] = 0ull;   // (0.f,0.f)

    float4 pA[2];
    auto loadChunk = [&](int kb) {
#pragma unroll
        for (int i = 0; i < 2; i++) {
            int f = t + 256 * i;        // 0..511
            int r = f >> 2, kq = f & 3; // r: row in tile, kq: k quad
            int gr = row0 + r;
            const float* src;
            if (DUAL && kb >= 128)
                src = A2 + (long long)gr * DIM + (kb - 128) + kq * 4;
            else
                src = A1 + (long long)gr * DIM + kb + kq * 4;
            pA[i] = (gr < M) ? *(const float4*)src
                             : make_float4(0.f, 0.f, 0.f, 0.f);
        }
    };
    loadChunk(0);

    constexpr int NCHUNK = KTOT / KC;
#pragma unroll 1
    for (int cb = 0; cb < NCHUNK; cb++) {
        __syncthreads();   // As readers done (also orders the W stores, iter 0)
#pragma unroll
        for (int i = 0; i < 2; i++) {
            int f = t + 256 * i;
            int r = f >> 2, kq = f & 3;
            As[(kq * 4 + 0) * AST + r] = pA[i].x;
            As[(kq * 4 + 1) * AST + r] = pA[i].y;
            As[(kq * 4 + 2) * AST + r] = pA[i].z;
            As[(kq * 4 + 3) * AST + r] = pA[i].w;
        }
        __syncthreads();
        if (cb + 1 < NCHUNK) loadChunk((cb + 1) * KC);   // prefetch next

#pragma unroll
        for (int kk = 0; kk < KC; kk++) {
            const int k = cb * KC + kk;
            float4 w0  = *(const float4*)&Ws[k * NC + c0];
            float4 w1v = *(const float4*)&Ws[k * NC + c0 + 4];
            unsigned long long wd[8];
            PACK2(wd[0], w0.x);  PACK2(wd[1], w0.y);
            PACK2(wd[2], w0.z);  PACK2(wd[3], w0.w);
            PACK2(wd[4], w1v.x); PACK2(wd[5], w1v.y);
            PACK2(wd[6], w1v.z); PACK2(wd[7], w1v.w);

            unsigned long long ap[NP];
#pragma unroll
            for (int p = 0; p < NP; p++)
                ap[p] = *(const unsigned long long*)&As[kk * AST + r0 + 2 * p];
#pragma unroll
            for (int p = 0; p < NP; p++)
#pragma unroll
                for (int j = 0; j < 8; j++)
                    FMA2(acc[p][j], ap[p], wd[j], acc[p][j]);
        }
    }

    // --- epilogue: unpack row pairs, bias, relu, vectorized store ---
#pragma unroll
    for (int p = 0; p < NP; p++) {
        float ev[8], ov[8];
#pragma unroll
        for (int j = 0; j < 8; j++) {
            float lo, hi;
            UNPACK2(lo, hi, acc[p][j]);
            lo += bs[j]; hi += bs[j];
            if (RELU) { lo = fmaxf(lo, 0.f); hi = fmaxf(hi, 0.f); }
            ev[j] = lo; ov[j] = hi;
        }
        int r = row0 + r0 + 2 * p;
        if (r < M) {
            float4* po = (float4*)&out[(long long)r * NC + c0];
            po[0] = make_float4(ev[0], ev[1], ev[2], ev[3]);
            po[1] = make_float4(ev[4], ev[5], ev[6], ev[7]);
        }
        if (r + 1 < M) {
            float4* po = (float4*)&out[(long long)(r + 1) * NC + c0];
            po[0] = make_float4(ov[0], ov[1], ov[2], ov[3]);
            po[1] = make_float4(ov[4], ov[5], ov[6], ov[7]);
        }
    }
}

// ---------------- launch ------------------------------------------------------
extern "C" void kernel_launch(void* const* d_in, const int* in_sizes, int n_in,
                              void* d_out, int out_size) {
    (void)in_sizes; (void)n_in; (void)out_size;
    const float* features = (const float*)d_in[0];
    const int*   src      = (const int*)  d_in[1];
    const int*   dst      = (const int*)  d_in[2];
    const float* W_self1  = (const float*)d_in[3];
    const float* W_neigh1 = (const float*)d_in[4];
    const float* b1       = (const float*)d_in[5];
    const float* W_self2  = (const float*)d_in[6];
    const float* W_neigh2 = (const float*)d_in[7];
    const float* b2       = (const float*)d_in[8];
    const float* W_out    = (const float*)d_in[9];
    const float* b_out    = (const float*)d_in[10];
    float*       out      = (float*)d_out;

    float *agg, *h1, *h2;
    cudaGetSymbolAddress((void**)&agg, g_agg);
    cudaGetSymbolAddress((void**)&h1,  g_h1);
    cudaGetSymbolAddress((void**)&h2,  g_h2);

    const int SMEM_L = 256 * 128 * 4 + 16 * 130 * 4;   // 139392 B
    const int SMEM_O = 128 * 64  * 4 + 16 * 130 * 4;   //  41088 B
    cudaFuncSetAttribute(gemm_kernel<256, 128, true, true>,
                         cudaFuncAttributeMaxDynamicSharedMemorySize, SMEM_L);

    const int EB = (N_EDGES + 255) / 256;   // 6250
    const int NB = (N_NODES + 255) / 256;   // 391
    const int GB = (N_NODES * 32 + 255) / 256;           // 12500 (warp/node)
    const int MB = (N_NODES + 127) / 128;   // 782

    // CSR build (once per launch, reused by both layers)
    zero_deg_kernel<<<NB, 256>>>();
    count_deg_kernel<<<EB, 256>>>(dst);
    scan_invdeg_kernel<<<1, 1024>>>();
    build_csr_kernel<<<EB, 256>>>(src, dst);

    // Layer 1
    gather_mean_kernel<<<GB, 256>>>(features, agg);
    gemm_kernel<256, 128, true, true><<<MB, 256, SMEM_L>>>(
        features, agg, W_self1, W_neigh1, b1, h1, N_NODES);

    // Layer 2
    gather_mean_kernel<<<GB, 256>>>(h1, agg);
    gemm_kernel<256, 128, true, true><<<MB, 256, SMEM_L>>>(
        h1, agg, W_self2, W_neigh2, b2, h2, N_NODES);

    // Output projection (no relu)
    gemm_kernel<128, 64, false, false><<<MB, 256, SMEM_O>>>(
        h2, nullptr, W_out, nullptr, b_out, out, N_NODES);
}

// round 3
// speedup vs baseline: 1.6909x; 1.6909x over previous
#include <cuda_runtime.h>
#include <cuda_bf16.h>
#include <cstdint>

#define N_NODES 100000
#define N_EDGES 1600000
#define DIM     128

// ---------------- scratch (device globals; no allocation in kernel_launch) ---
__device__ int   g_deg[N_NODES];
__device__ int   g_off[N_NODES + 1];
__device__ int   g_cur[N_NODES];
__device__ int   g_csr[N_EDGES];
__device__ float g_invdeg[N_NODES];
__device__ int   g_bsum[512];
__device__ int   g_bpre[512];
__device__ float g_agg[(long long)N_NODES * DIM];
__device__ float g_h1 [(long long)N_NODES * DIM];
__device__ float g_h2 [(long long)N_NODES * DIM];

// ---------------- CSR build --------------------------------------------------
__global__ void zero_deg_kernel() {
    int i = blockIdx.x * blockDim.x + threadIdx.x;
    if (i < N_NODES) g_deg[i] = 0;
}
__global__ void count_deg_kernel(const int* __restrict__ dst) {
    int i = blockIdx.x * blockDim.x + threadIdx.x;
    if (i < N_EDGES) atomicAdd(&g_deg[dst[i]], 1);
}
__global__ void degsum_kernel() {
    __shared__ int sh[256];
    int b = blockIdx.x, t = threadIdx.x;
    int i = b * 256 + t;
    sh[t] = (i < N_NODES) ? g_deg[i] : 0;
    __syncthreads();
    for (int d = 128; d > 0; d >>= 1) {
        if (t < d) sh[t] += sh[t + d];
        __syncthreads();
    }
    if (t == 0) g_bsum[b] = sh[0];
}
__global__ void scanb_kernel(int nb) {   // 1 block, 512 threads (nb <= 512)
    __shared__ int sh[512];
    int t = threadIdx.x;
    int v0 = (t < nb) ? g_bsum[t] : 0;
    sh[t] = v0;
    __syncthreads();
    for (int d = 1; d < 512; d <<= 1) {
        int v = (t >= d) ? sh[t - d] : 0;
        __syncthreads();
        sh[t] += v;
        __syncthreads();
    }
    if (t < nb) g_bpre[t] = sh[t] - v0;   // exclusive prefix
}
__global__ void writeoff_kernel() {
    __shared__ int sh[256];
    int b = blockIdx.x, t = threadIdx.x;
    int i = b * 256 + t;
    int dg = (i < N_NODES) ? g_deg[i] : 0;
    sh[t] = dg;
    __syncthreads();
    for (int d = 1; d < 256; d <<= 1) {
        int v = (t >= d) ? sh[t - d] : 0;
        __syncthreads();
        sh[t] += v;
        __syncthreads();
    }
    if (i < N_NODES) {
        int off = g_bpre[b] + sh[t] - dg;
        g_off[i] = off;
        g_cur[i] = off;
        g_invdeg[i] = 1.0f / (float)(dg > 0 ? dg : 1);
        if (i == N_NODES - 1) g_off[N_NODES] = off + dg;
    }
}
__global__ void build_csr_kernel(const int* __restrict__ src,
                                 const int* __restrict__ dst) {
    int i = blockIdx.x * blockDim.x + threadIdx.x;
    if (i < N_EDGES) {
        int d = dst[i];
        int p = atomicAdd(&g_cur[d], 1);
        g_csr[p] = src[i];
    }
}

// ---------------- gather-side mean aggregation (warp per node) ---------------
__global__ void gather_mean_kernel(const float* __restrict__ h,
                                   float* __restrict__ out) {
    int warp = (blockIdx.x * blockDim.x + threadIdx.x) >> 5;
    if (warp >= N_NODES) return;
    int lane = threadIdx.x & 31;
    int s0 = g_off[warp];
    int s1 = g_off[warp + 1];
    float4 acc = make_float4(0.f, 0.f, 0.f, 0.f);
    for (int e = s0; e < s1; e += 32) {
        int idx = (e + lane < s1) ? g_csr[e + lane] : 0;
        int cnt = s1 - e; if (cnt > 32) cnt = 32;
        int j = 0;
        for (; j + 4 <= cnt; j += 4) {
            int i0 = __shfl_sync(0xffffffffu, idx, j + 0);
            int i1 = __shfl_sync(0xffffffffu, idx, j + 1);
            int i2 = __shfl_sync(0xffffffffu, idx, j + 2);
            int i3 = __shfl_sync(0xffffffffu, idx, j + 3);
            float4 v0 = *(const float4*)(h + (long long)i0 * DIM + lane * 4);
            float4 v1 = *(const float4*)(h + (long long)i1 * DIM + lane * 4);
            float4 v2 = *(const float4*)(h + (long long)i2 * DIM + lane * 4);
            float4 v3 = *(const float4*)(h + (long long)i3 * DIM + lane * 4);
            acc.x += v0.x; acc.y += v0.y; acc.z += v0.z; acc.w += v0.w;
            acc.x += v1.x; acc.y += v1.y; acc.z += v1.z; acc.w += v1.w;
            acc.x += v2.x; acc.y += v2.y; acc.z += v2.z; acc.w += v2.w;
            acc.x += v3.x; acc.y += v3.y; acc.z += v3.z; acc.w += v3.w;
        }
        for (; j < cnt; j++) {
            int s = __shfl_sync(0xffffffffu, idx, j);
            float4 v = *(const float4*)(h + (long long)s * DIM + lane * 4);
            acc.x += v.x; acc.y += v.y; acc.z += v.z; acc.w += v.w;
        }
    }
    float inv = g_invdeg[warp];
    float4 r = make_float4(acc.x * inv, acc.y * inv, acc.z * inv, acc.w * inv);
    *(float4*)(out + (long long)warp * DIM + lane * 4) = r;
}

// ---------------- mma.sync bf16-split GEMM -----------------------------------
// out[M, NTILE] = act( [A1 | A2] @ [W1 ; W2] + bias )
// bf16 error split: D = Ah*Wh + Ah*Wl + Al*Wh  (drop Al*Wl, rel err ~1.5e-5).
// CTA: 128 rows x NTILE cols, 256 threads (8 warps), mma.sync m16n8k16.

#define MMA_BF16(d, a, b)                                                     \
    asm volatile(                                                             \
        "mma.sync.aligned.m16n8k16.row.col.f32.bf16.bf16.f32 "                \
        "{%0,%1,%2,%3}, {%4,%5,%6,%7}, {%8,%9}, {%0,%1,%2,%3};"               \
        : "+f"((d)[0]), "+f"((d)[1]), "+f"((d)[2]), "+f"((d)[3])              \
        : "r"((a)[0]), "r"((a)[1]), "r"((a)[2]), "r"((a)[3]),                 \
          "r"((b)[0]), "r"((b)[1]))

template <int KTOT, int NTILE, bool RELU, bool DUAL>
__global__ void __launch_bounds__(256, 1)
mma_gemm(const float* __restrict__ A1, const float* __restrict__ A2,
         const float* __restrict__ W1, const float* __restrict__ W2,
         const float* __restrict__ bias, float* __restrict__ out, int M) {
    constexpr int COLW = NTILE / 64;        // warp col-groups (2 or 1)
    constexpr int ROWG = 8 / COLW;          // warp row-groups (4 or 8)
    constexpr int RPW  = 128 / ROWG;        // rows per warp (32 or 16)
    constexpr int MF   = RPW / 16;          // m16 frags per warp (2 or 1)
    constexpr int KC     = 64;              // k chunk
    constexpr int NCHUNK = KTOT / KC;
    constexpr int SA = KC + 8;              // padded A stride (bf16 elems)
    constexpr int SB = KTOT + 8;            // padded Wt stride

    extern __shared__ __align__(16) __nv_bfloat16 smem[];
    __nv_bfloat16* WH = smem;                        // [NTILE][SB]
    __nv_bfloat16* WL = WH + NTILE * SB;
    __nv_bfloat16* AH = WL + NTILE * SB;             // [2 stages][128][SA]
    __nv_bfloat16* AL = AH + 2 * 128 * SA;

    const int tid  = threadIdx.x;
    const int wid  = tid >> 5;
    const int lane = tid & 31;
    const int g    = lane >> 2;             // fragment group row/col
    const int tq   = lane & 3;              // fragment quad idx
    const int row0 = blockIdx.x * 128;

    // --- stage W transposed [n][k], split hi/lo ---
    for (int idx = tid; idx < KTOT * NTILE; idx += 256) {
        int k = idx / NTILE, n = idx % NTILE;
        float w = (DUAL && k >= 128) ? W2[(k - 128) * NTILE + n]
                                     : W1[k * NTILE + n];
        __nv_bfloat16 h = __float2bfloat16(w);
        __nv_bfloat16 l = __float2bfloat16(w - __bfloat162float(h));
        WH[n * SB + k] = h;
        WL[n * SB + k] = l;
    }

    // --- A chunk staging: fp32 -> hi/lo bf16 into stage s ---
    auto stageA = [&](int c, int s) {
        const float* base; int kb;
        if (DUAL && c >= 2) { base = A2; kb = (c - 2) * KC; }
        else                { base = A1; kb = c * KC; }
        __nv_bfloat16* ah = AH + s * 128 * SA;
        __nv_bfloat16* al = AL + s * 128 * SA;
#pragma unroll
        for (int it = 0; it < 8; it++) {
            int idx = tid + it * 256;        // 0..2047 (128 rows x 16 quads)
            int r = idx >> 4, q = idx & 15;
            int gr = row0 + r;
            float4 v = make_float4(0.f, 0.f, 0.f, 0.f);
            if (gr < M) v = *(const float4*)(base + (long long)gr * DIM + kb + q * 4);
            float f[4] = {v.x, v.y, v.z, v.w};
            unsigned long long hp = 0ull, lp = 0ull;
#pragma unroll
            for (int j = 0; j < 4; j++) {
                __nv_bfloat16 h = __float2bfloat16(f[j]);
                __nv_bfloat16 l = __float2bfloat16(f[j] - __bfloat162float(h));
                hp |= (unsigned long long)__bfloat16_as_ushort(h) << (16 * j);
                lp |= (unsigned long long)__bfloat16_as_ushort(l) << (16 * j);
            }
            *(unsigned long long*)(ah + r * SA + q * 4) = hp;
            *(unsigned long long*)(al + r * SA + q * 4) = lp;
        }
    };

    const int cw = wid % COLW;              // warp col group
    const int rw = wid / COLW;              // warp row group
    const int n0 = cw * 64;
    const int wr0 = rw * RPW;

    float acc[MF][8][4];
#pragma unroll
    for (int mf = 0; mf < MF; mf++)
#pragma unroll
        for (int nf = 0; nf < 8; nf++)
#pragma unroll
            for (int j = 0; j < 4; j++) acc[mf][nf][j] = 0.f;

    stageA(0, 0);
    __syncthreads();

#pragma unroll 1
    for (int c = 0; c < NCHUNK; c++) {
        // stage next chunk first: LDGs fly under this chunk's MMA work.
        if (c + 1 < NCHUNK) stageA(c + 1, (c + 1) & 1);

        const __nv_bfloat16* ah = AH + (c & 1) * 128 * SA;
        const __nv_bfloat16* al = AL + (c & 1) * 128 * SA;
#pragma unroll
        for (int ks = 0; ks < KC / 16; ks++) {
            const int k0 = ks * 16;          // within chunk (A)
            const int kg = c * KC + k0;      // global k (W)

            uint32_t afh[MF][4], afl[MF][4];
#pragma unroll
            for (int mf = 0; mf < MF; mf++) {
                int r = wr0 + mf * 16 + g;
                afh[mf][0] = *(const uint32_t*)(ah + r * SA + k0 + 2 * tq);
                afh[mf][1] = *(const uint32_t*)(ah + (r + 8) * SA + k0 + 2 * tq);
                afh[mf][2] = *(const uint32_t*)(ah + r * SA + k0 + 8 + 2 * tq);
                afh[mf][3] = *(const uint32_t*)(ah + (r + 8) * SA + k0 + 8 + 2 * tq);
                afl[mf][0] = *(const uint32_t*)(al + r * SA + k0 + 2 * tq);
                afl[mf][1] = *(const uint32_t*)(al + (r + 8) * SA + k0 + 2 * tq);
                afl[mf][2] = *(const uint32_t*)(al + r * SA + k0 + 8 + 2 * tq);
                afl[mf][3] = *(const uint32_t*)(al + (r + 8) * SA + k0 + 8 + 2 * tq);
            }
#pragma unroll
            for (int nf = 0; nf < 8; nf++) {
                int n = n0 + nf * 8 + g;
                uint32_t bh[2], bl[2];
                bh[0] = *(const uint32_t*)(WH + n * SB + kg + 2 * tq);
                bh[1] = *(const uint32_t*)(WH + n * SB + kg + 8 + 2 * tq);
                bl[0] = *(const uint32_t*)(WL + n * SB + kg + 2 * tq);
                bl[1] = *(const uint32_t*)(WL + n * SB + kg + 8 + 2 * tq);
#pragma unroll
                for (int mf = 0; mf < MF; mf++) {
                    MMA_BF16(acc[mf][nf], afh[mf], bh);
                    MMA_BF16(acc[mf][nf], afh[mf], bl);
                    MMA_BF16(acc[mf][nf], afl[mf], bh);
                }
            }
        }
        __syncthreads();
    }

    // --- epilogue: bias (+relu), fragment layout -> global ---
#pragma unroll
    for (int mf = 0; mf < MF; mf++) {
#pragma unroll
        for (int nf = 0; nf < 8; nf++) {
            int col = n0 + nf * 8 + 2 * tq;
            float b0 = __ldg(&bias[col]);
            float b1 = __ldg(&bias[col + 1]);
            int r = row0 + wr0 + mf * 16 + g;
            float v0 = acc[mf][nf][0] + b0, v1 = acc[mf][nf][1] + b1;
            float v2 = acc[mf][nf][2] + b0, v3 = acc[mf][nf][3] + b1;
            if (RELU) {
                v0 = fmaxf(v0, 0.f); v1 = fmaxf(v1, 0.f);
                v2 = fmaxf(v2, 0.f); v3 = fmaxf(v3, 0.f);
            }
            if (r < M)
                *(float2*)(out + (long long)r * NTILE + col) = make_float2(v0, v1);
            if (r + 8 < M)
                *(float2*)(out + (long long)(r + 8) * NTILE + col) = make_float2(v2, v3);
        }
    }
}

// ---------------- launch ------------------------------------------------------
extern "C" void kernel_launch(void* const* d_in, const int* in_sizes, int n_in,
                              void* d_out, int out_size) {
    (void)in_sizes; (void)n_in; (void)out_size;
    const float* features = (const float*)d_in[0];
    const int*   src      = (const int*)  d_in[1];
    const int*   dst      = (const int*)  d_in[2];
    const float* W_self1  = (const float*)d_in[3];
    const float* W_neigh1 = (const float*)d_in[4];
    const float* b1       = (const float*)d_in[5];
    const float* W_self2  = (const float*)d_in[6];
    const float* W_neigh2 = (const float*)d_in[7];
    const float* b2       = (const float*)d_in[8];
    const float* W_out    = (const float*)d_in[9];
    const float* b_out    = (const float*)d_in[10];
    float*       out      = (float*)d_out;

    float *agg, *h1, *h2;
    cudaGetSymbolAddress((void**)&agg, g_agg);
    cudaGetSymbolAddress((void**)&h1,  g_h1);
    cudaGetSymbolAddress((void**)&h2,  g_h2);

    // smem bytes: 2 W planes [NTILE][KTOT+8] + 2x2 A stages [128][72], bf16
    const int SMEM_L = (2 * 128 * (256 + 8) + 4 * 128 * 72) * 2;  // 208896
    const int SMEM_O = (2 * 64  * (128 + 8) + 4 * 128 * 72) * 2;  // 108544
    cudaFuncSetAttribute(mma_gemm<256, 128, true, true>,
                         cudaFuncAttributeMaxDynamicSharedMemorySize, SMEM_L);
    cudaFuncSetAttribute(mma_gemm<128, 64, false, false>,
                         cudaFuncAttributeMaxDynamicSharedMemorySize, SMEM_O);

    const int EB = (N_EDGES + 255) / 256;          // 6250
    const int NB = (N_NODES + 255) / 256;          // 391
    const int GB = (N_NODES * 32 + 255) / 256;     // 12500 (warp per node)
    const int MB = (N_NODES + 127) / 128;          // 782

    // CSR build (parallel scan)
    zero_deg_kernel<<<NB, 256>>>();
    count_deg_kernel<<<EB, 256>>>(dst);
    degsum_kernel<<<NB, 256>>>();
    scanb_kernel<<<1, 512>>>(NB);
    writeoff_kernel<<<NB, 256>>>();
    build_csr_kernel<<<EB, 256>>>(src, dst);

    // Layer 1
    gather_mean_kernel<<<GB, 256>>>(features, agg);
    mma_gemm<256, 128, true, true><<<MB, 256, SMEM_L>>>(
        features, agg, W_self1, W_neigh1, b1, h1, N_NODES);

    // Layer 2
    gather_mean_kernel<<<GB, 256>>>(h1, agg);
    mma_gemm<256, 128, true, true><<<MB, 256, SMEM_L>>>(
        h1, agg, W_self2, W_neigh2, b2, h2, N_NODES);

    // Output projection
    mma_gemm<128, 64, false, false><<<MB, 256, SMEM_O>>>(
        h2, nullptr, W_out, nullptr, b_out, out, N_NODES);
}

// round 6
// speedup vs baseline: 1.7663x; 1.0446x over previous
#include <cuda_runtime.h>
#include <cuda_bf16.h>
#include <cuda_fp16.h>
#include <cstdint>

#define N_NODES 100000
#define N_EDGES 1600000
#define DIM     128

// ---------------- scratch (device globals; no allocation in kernel_launch) ---
__device__ int   g_deg[N_NODES];
__device__ int   g_off[N_NODES + 1];
__device__ int   g_cur[N_NODES];
__device__ int   g_csr[N_EDGES];
__device__ float g_invdeg[N_NODES];
__device__ int   g_bsum[512];
__device__ int   g_bpre[512];
__device__ float g_agg[(long long)N_NODES * DIM];
__device__ float g_h1 [(long long)N_NODES * DIM];
__device__ float g_h2 [(long long)N_NODES * DIM];
__device__ __half g_p16[(long long)N_NODES * DIM];   // fp16 gather plane (reused)

// ---------------- CSR build --------------------------------------------------
__global__ void zero_deg_kernel() {
    int i = blockIdx.x * blockDim.x + threadIdx.x;
    if (i < N_NODES) g_deg[i] = 0;
}
__global__ void count_deg_kernel(const int* __restrict__ dst) {
    int i = blockIdx.x * blockDim.x + threadIdx.x;
    if (i < N_EDGES) atomicAdd(&g_deg[dst[i]], 1);
}
__global__ void degsum_kernel() {
    __shared__ int sh[256];
    int b = blockIdx.x, t = threadIdx.x;
    int i = b * 256 + t;
    sh[t] = (i < N_NODES) ? g_deg[i] : 0;
    __syncthreads();
    for (int d = 128; d > 0; d >>= 1) {
        if (t < d) sh[t] += sh[t + d];
        __syncthreads();
    }
    if (t == 0) g_bsum[b] = sh[0];
}
__global__ void scanb_kernel(int nb) {
    __shared__ int sh[512];
    int t = threadIdx.x;
    int v0 = (t < nb) ? g_bsum[t] : 0;
    sh[t] = v0;
    __syncthreads();
    for (int d = 1; d < 512; d <<= 1) {
        int v = (t >= d) ? sh[t - d] : 0;
        __syncthreads();
        sh[t] += v;
        __syncthreads();
    }
    if (t < nb) g_bpre[t] = sh[t] - v0;
}
__global__ void writeoff_kernel() {
    __shared__ int sh[256];
    int b = blockIdx.x, t = threadIdx.x;
    int i = b * 256 + t;
    int dg = (i < N_NODES) ? g_deg[i] : 0;
    sh[t] = dg;
    __syncthreads();
    for (int d = 1; d < 256; d <<= 1) {
        int v = (t >= d) ? sh[t - d] : 0;
        __syncthreads();
        sh[t] += v;
        __syncthreads();
    }
    if (i < N_NODES) {
        int off = g_bpre[b] + sh[t] - dg;
        g_off[i] = off;
        g_cur[i] = off;
        g_invdeg[i] = 1.0f / (float)(dg > 0 ? dg : 1);
        if (i == N_NODES - 1) g_off[N_NODES] = off + dg;
    }
}
__global__ void build_csr_kernel(const int* __restrict__ src,
                                 const int* __restrict__ dst) {
    int i = blockIdx.x * blockDim.x + threadIdx.x;
    if (i < N_EDGES) {
        int d = dst[i];
        int p = atomicAdd(&g_cur[d], 1);
        g_csr[p] = src[i];
    }
}

// ---------------- fp32 -> fp16 plane conversion ------------------------------
__global__ void to_f16_kernel(const float* __restrict__ in,
                              __half* __restrict__ out, int n4) {
    int i = blockIdx.x * blockDim.x + threadIdx.x;
    if (i < n4) {
        float4 v = *(const float4*)(in + (long long)i * 4);
        __half2 h0 = __floats2half2_rn(v.x, v.y);
        __half2 h1 = __floats2half2_rn(v.z, v.w);
        *(__half2*)(out + (long long)i * 4)     = h0;
        *(__half2*)(out + (long long)i * 4 + 2) = h1;
    }
}

// ---------------- gather-side mean aggregation (warp per node, fp16 src) -----
__global__ void gather_mean_f16_kernel(const __half* __restrict__ hsrc,
                                       float* __restrict__ out) {
    int warp = (blockIdx.x * blockDim.x + threadIdx.x) >> 5;
    if (warp >= N_NODES) return;
    int lane = threadIdx.x & 31;
    int s0 = g_off[warp];
    int s1 = g_off[warp + 1];
    float4 acc = make_float4(0.f, 0.f, 0.f, 0.f);

    auto addRow = [&](int node) {
        uint2 raw = *(const uint2*)(hsrc + (long long)node * DIM + lane * 4);
        __half2 p0 = *(__half2*)&raw.x;
        __half2 p1 = *(__half2*)&raw.y;
        float2 f0 = __half22float2(p0);
        float2 f1 = __half22float2(p1);
        acc.x += f0.x; acc.y += f0.y; acc.z += f1.x; acc.w += f1.y;
    };

    for (int e = s0; e < s1; e += 32) {
        int idx = (e + lane < s1) ? g_csr[e + lane] : 0;
        int cnt = s1 - e; if (cnt > 32) cnt = 32;
        int j = 0;
        for (; j + 4 <= cnt; j += 4) {
            int i0 = __shfl_sync(0xffffffffu, idx, j + 0);
            int i1 = __shfl_sync(0xffffffffu, idx, j + 1);
            int i2 = __shfl_sync(0xffffffffu, idx, j + 2);
            int i3 = __shfl_sync(0xffffffffu, idx, j + 3);
            addRow(i0); addRow(i1); addRow(i2); addRow(i3);
        }
        for (; j < cnt; j++) addRow(__shfl_sync(0xffffffffu, idx, j));
    }
    float inv = g_invdeg[warp];
    float4 r = make_float4(acc.x * inv, acc.y * inv, acc.z * inv, acc.w * inv);
    *(float4*)(out + (long long)warp * DIM + lane * 4) = r;
}

// ---------------- mma.sync bf16-split GEMM (ldmatrix fragments) --------------
// out[M, NTILE] = act( [A1 | A2] @ [W1 ; W2] + bias ); optional fp16 plane out.
// D = Ah*Wh + Ah*Wl + Al*Wh  (drop Al*Wl, rel err ~1.5e-5).

#define MMA_BF16(d, a, b)                                                     \
    asm volatile(                                                             \
        "mma.sync.aligned.m16n8k16.row.col.f32.bf16.bf16.f32 "                \
        "{%0,%1,%2,%3}, {%4,%5,%6,%7}, {%8,%9}, {%0,%1,%2,%3};"               \
        : "+f"((d)[0]), "+f"((d)[1]), "+f"((d)[2]), "+f"((d)[3])              \
        : "r"((a)[0]), "r"((a)[1]), "r"((a)[2]), "r"((a)[3]),                 \
          "r"((b)[0]), "r"((b)[1]))

#define LDSM_X4(r0, r1, r2, r3, addr)                                         \
    asm volatile("ldmatrix.sync.aligned.m8n8.x4.shared.b16 {%0,%1,%2,%3}, [%4];" \
        : "=r"(r0), "=r"(r1), "=r"(r2), "=r"(r3) : "r"(addr))

__device__ __forceinline__ uint32_t smem_u32(const void* p) {
    uint32_t a;
    asm("{ .reg .u64 t; cvta.to.shared.u64 t, %1; cvt.u32.u64 %0, t; }"
        : "=r"(a) : "l"(p));
    return a;
}

template <int KTOT, int NTILE, bool RELU, bool DUAL, bool WF16>
__global__ void __launch_bounds__(256, 1)
mma_gemm(const float* __restrict__ A1, const float* __restrict__ A2,
         const float* __restrict__ W1, const float* __restrict__ W2,
         const float* __restrict__ bias, float* __restrict__ out,
         __half* __restrict__ out16, int M) {
    constexpr int COLW = NTILE / 64;        // warp col-groups (2 or 1)
    constexpr int ROWG = 8 / COLW;          // warp row-groups (4 or 8)
    constexpr int RPW  = 128 / ROWG;        // rows per warp (32 or 16)
    constexpr int MF   = RPW / 16;          // m16 frags per warp (2 or 1)
    constexpr int KC     = 64;
    constexpr int NCHUNK = KTOT / KC;
    constexpr int SA = KC + 8;              // padded A stride (bf16 elems)
    constexpr int SB = KTOT + 8;            // padded Wt stride

    extern __shared__ __align__(16) __nv_bfloat16 smem[];
    __nv_bfloat16* WH = smem;                        // [NTILE][SB]
    __nv_bfloat16* WL = WH + NTILE * SB;
    __nv_bfloat16* AH = WL + NTILE * SB;             // [2 stages][128][SA]
    __nv_bfloat16* AL = AH + 2 * 128 * SA;

    const uint32_t sbase = smem_u32(smem);
    const int tid  = threadIdx.x;
    const int wid  = tid >> 5;
    const int lane = tid & 31;
    const int g    = lane >> 2;
    const int tq   = lane & 3;
    const int l8   = lane & 7;
    const int sel  = lane >> 3;             // ldmatrix mat select 0..3
    const int row0 = blockIdx.x * 128;

    // --- stage W transposed [n][k], split hi/lo ---
    for (int idx = tid; idx < KTOT * NTILE; idx += 256) {
        int k = idx / NTILE, n = idx % NTILE;
        float w = (DUAL && k >= 128) ? W2[(k - 128) * NTILE + n]
                                     : W1[k * NTILE + n];
        __nv_bfloat16 h = __float2bfloat16(w);
        __nv_bfloat16 l = __float2bfloat16(w - __bfloat162float(h));
        WH[n * SB + k] = h;
        WL[n * SB + k] = l;
    }

    auto stageA = [&](int c, int s) {
        const float* base; int kb;
        if (DUAL && c >= 2) { base = A2; kb = (c - 2) * KC; }
        else                { base = A1; kb = c * KC; }
        __nv_bfloat16* ah = AH + s * 128 * SA;
        __nv_bfloat16* al = AL + s * 128 * SA;
#pragma unroll
        for (int it = 0; it < 8; it++) {
            int idx = tid + it * 256;        // 128 rows x 16 quads
            int r = idx >> 4, q = idx & 15;
            int gr = row0 + r;
            float4 v = make_float4(0.f, 0.f, 0.f, 0.f);
            if (gr < M) v = *(const float4*)(base + (long long)gr * DIM + kb + q * 4);
            float f[4] = {v.x, v.y, v.z, v.w};
            unsigned long long hp = 0ull, lp = 0ull;
#pragma unroll
            for (int j = 0; j < 4; j++) {
                __nv_bfloat16 h = __float2bfloat16(f[j]);
                __nv_bfloat16 l = __float2bfloat16(f[j] - __bfloat162float(h));
                hp |= (unsigned long long)__bfloat16_as_ushort(h) << (16 * j);
                lp |= (unsigned long long)__bfloat16_as_ushort(l) << (16 * j);
            }
            *(unsigned long long*)(ah + r * SA + q * 4) = hp;
            *(unsigned long long*)(al + r * SA + q * 4) = lp;
        }
    };

    const int cw = wid % COLW;
    const int rw = wid / COLW;
    const int n0 = cw * 64;
    const int wr0 = rw * RPW;

    // ldmatrix lane-address components (element offsets)
    // A mats: {m,k0}, {m+8,k0}, {m,k0+8}, {m+8,k0+8}
    const int a_row_l = l8 + ((sel & 1) << 3);       // within warp-tile rows
    const int a_kadd  = (sel >> 1) << 3;
    // B mats for nf pair: {n,kg}, {n,kg+8}, {n+8,kg}, {n+8,kg+8}
    const int b_row_l = l8 + ((sel >> 1) << 3);
    const int b_kadd  = (sel & 1) << 3;

    float acc[MF][8][4];
#pragma unroll
    for (int mf = 0; mf < MF; mf++)
#pragma unroll
        for (int nf = 0; nf < 8; nf++)
#pragma unroll
            for (int j = 0; j < 4; j++) acc[mf][nf][j] = 0.f;

    stageA(0, 0);
    __syncthreads();

    const uint32_t whB = sbase;                                  // WH bytes
    const uint32_t wlB = sbase + (uint32_t)(NTILE * SB) * 2;     // WL bytes
    const uint32_t ahB = wlB + (uint32_t)(NTILE * SB) * 2;       // AH bytes
    const uint32_t alB = ahB + (uint32_t)(2 * 128 * SA) * 2;     // AL bytes

#pragma unroll 1
    for (int c = 0; c < NCHUNK; c++) {
        if (c + 1 < NCHUNK) stageA(c + 1, (c + 1) & 1);

        const uint32_t ast = (uint32_t)((c & 1) * 128 * SA) * 2;
#pragma unroll
        for (int ks = 0; ks < KC / 16; ks++) {
            const int k0 = ks * 16;
            const int kg = c * KC + k0;

            uint32_t afh[MF][4], afl[MF][4];
#pragma unroll
            for (int mf = 0; mf < MF; mf++) {
                uint32_t ao = (uint32_t)((wr0 + mf * 16 + a_row_l) * SA
                                         + k0 + a_kadd) * 2;
                LDSM_X4(afh[mf][0], afh[mf][1], afh[mf][2], afh[mf][3],
                        ahB + ast + ao);
                LDSM_X4(afl[mf][0], afl[mf][1], afl[mf][2], afl[mf][3],
                        alB + ast + ao);
            }
            uint32_t bh[8][2], bl[8][2];
#pragma unroll
            for (int nfp = 0; nfp < 4; nfp++) {
                uint32_t bo = (uint32_t)((n0 + nfp * 16 + b_row_l) * SB
                                         + kg + b_kadd) * 2;
                LDSM_X4(bh[2 * nfp][0], bh[2 * nfp][1],
                        bh[2 * nfp + 1][0], bh[2 * nfp + 1][1], whB + bo);
                LDSM_X4(bl[2 * nfp][0], bl[2 * nfp][1],
                        bl[2 * nfp + 1][0], bl[2 * nfp + 1][1], wlB + bo);
            }
#pragma unroll
            for (int nf = 0; nf < 8; nf++)
#pragma unroll
                for (int mf = 0; mf < MF; mf++) {
                    MMA_BF16(acc[mf][nf], afh[mf], bh[nf]);
                    MMA_BF16(acc[mf][nf], afh[mf], bl[nf]);
                    MMA_BF16(acc[mf][nf], afl[mf], bh[nf]);
                }
        }
        __syncthreads();
    }

    // --- epilogue: bias (+relu), optional fp16 plane, store ---
#pragma unroll
    for (int mf = 0; mf < MF; mf++) {
#pragma unroll
        for (int nf = 0; nf < 8; nf++) {
            int col = n0 + nf * 8 + 2 * tq;
            float b0 = __ldg(&bias[col]);
            float b1 = __ldg(&bias[col + 1]);
            int r = row0 + wr0 + mf * 16 + g;
            float v0 = acc[mf][nf][0] + b0, v1 = acc[mf][nf][1] + b1;
            float v2 = acc[mf][nf][2] + b0, v3 = acc[mf][nf][3] + b1;
            if (RELU) {
                v0 = fmaxf(v0, 0.f); v1 = fmaxf(v1, 0.f);
                v2 = fmaxf(v2, 0.f); v3 = fmaxf(v3, 0.f);
            }
            if (r < M) {
                *(float2*)(out + (long long)r * NTILE + col) = make_float2(v0, v1);
                if (WF16)
                    *(__half2*)(out16 + (long long)r * NTILE + col) =
                        __floats2half2_rn(v0, v1);
            }
            if (r + 8 < M) {
                *(float2*)(out + (long long)(r + 8) * NTILE + col) = make_float2(v2, v3);
                if (WF16)
                    *(__half2*)(out16 + (long long)(r + 8) * NTILE + col) =
                        __floats2half2_rn(v2, v3);
            }
        }
    }
}

// ---------------- launch ------------------------------------------------------
extern "C" void kernel_launch(void* const* d_in, const int* in_sizes, int n_in,
                              void* d_out, int out_size) {
    (void)in_sizes; (void)n_in; (void)out_size;
    const float* features = (const float*)d_in[0];
    const int*   src      = (const int*)  d_in[1];
    const int*   dst      = (const int*)  d_in[2];
    const float* W_self1  = (const float*)d_in[3];
    const float* W_neigh1 = (const float*)d_in[4];
    const float* b1       = (const float*)d_in[5];
    const float* W_self2  = (const float*)d_in[6];
    const float* W_neigh2 = (const float*)d_in[7];
    const float* b2       = (const float*)d_in[8];
    const float* W_out    = (const float*)d_in[9];
    const float* b_out    = (const float*)d_in[10];
    float*       out      = (float*)d_out;

    float *agg, *h1, *h2; __half* p16;
    cudaGetSymbolAddress((void**)&agg, g_agg);
    cudaGetSymbolAddress((void**)&h1,  g_h1);
    cudaGetSymbolAddress((void**)&h2,  g_h2);
    cudaGetSymbolAddress((void**)&p16, g_p16);

    const int SMEM_L = (2 * 128 * (256 + 8) + 4 * 128 * 72) * 2;  // 208896
    const int SMEM_O = (2 * 64  * (128 + 8) + 4 * 128 * 72) * 2;  // 108544
    cudaFuncSetAttribute(mma_gemm<256, 128, true, true, true>,
                         cudaFuncAttributeMaxDynamicSharedMemorySize, SMEM_L);
    cudaFuncSetAttribute(mma_gemm<256, 128, true, true, false>,
                         cudaFuncAttributeMaxDynamicSharedMemorySize, SMEM_L);
    cudaFuncSetAttribute(mma_gemm<128, 64, false, false, false>,
                         cudaFuncAttributeMaxDynamicSharedMemorySize, SMEM_O);

    const int EB = (N_EDGES + 255) / 256;          // 6250
    const int NB = (N_NODES + 255) / 256;          // 391
    const int GB = (N_NODES * 32 + 255) / 256;     // 12500 (warp per node)
    const int MB = (N_NODES + 127) / 128;          // 782
    const int CB = (N_NODES * DIM / 4 + 255) / 256;

    // features -> fp16 plane; CSR build (parallel scan)
    to_f16_kernel<<<CB, 256>>>(features, p16, N_NODES * DIM / 4);
    zero_deg_kernel<<<NB, 256>>>();
    count_deg_kernel<<<EB, 256>>>(dst);
    degsum_kernel<<<NB, 256>>>();
    scanb_kernel<<<1, 512>>>(NB);
    writeoff_kernel<<<NB, 256>>>();
    build_csr_kernel<<<EB, 256>>>(src, dst);

    // Layer 1 (gemm writes h1 fp32 + fp16 plane for layer-2 gather)
    gather_mean_f16_kernel<<<GB, 256>>>(p16, agg);
    mma_gemm<256, 128, true, true, true><<<MB, 256, SMEM_L>>>(
        features, agg, W_self1, W_neigh1, b1, h1, p16, N_NODES);

    // Layer 2
    gather_mean_f16_kernel<<<GB, 256>>>(p16, agg);
    mma_gemm<256, 128, true, true, false><<<MB, 256, SMEM_L>>>(
        h1, agg, W_self2, W_neigh2, b2, h2, nullptr, N_NODES);

    // Output projection
    mma_gemm<128, 64, false, false, false><<<MB, 256, SMEM_O>>>(
        h2, nullptr, W_out, nullptr, b_out, out, nullptr, N_NODES);
}

// round 7
// speedup vs baseline: 2.0761x; 1.1754x over previous
#include <cuda_runtime.h>
#include <cuda_bf16.h>
#include <cuda_fp16.h>
#include <cstdint>

#define N_NODES 100000
#define N_EDGES 1600000
#define DIM     128

// ---------------- scratch (device globals; no allocation in kernel_launch) ---
__device__ int   g_deg[N_NODES];
__device__ int   g_off[N_NODES + 1];
__device__ int   g_cur[N_NODES];
__device__ int   g_csr[N_EDGES];
__device__ float g_invdeg[N_NODES];
__device__ int   g_bsum[512];
__device__ float g_agg[(long long)N_NODES * DIM];
__device__ float g_h1 [(long long)N_NODES * DIM];
__device__ float g_h2 [(long long)N_NODES * DIM];
__device__ __half g_p16[(long long)N_NODES * DIM];   // fp16 gather plane (reused)

// ---------------- CSR build --------------------------------------------------
__global__ void count_deg_kernel(const int* __restrict__ dst) {
    int i = blockIdx.x * blockDim.x + threadIdx.x;
    if (i < N_EDGES) atomicAdd(&g_deg[dst[i]], 1);
}
__global__ void degsum_kernel() {
    __shared__ int sh[256];
    int b = blockIdx.x, t = threadIdx.x;
    int i = b * 256 + t;
    sh[t] = (i < N_NODES) ? g_deg[i] : 0;
    __syncthreads();
    for (int d = 128; d > 0; d >>= 1) {
        if (t < d) sh[t] += sh[t + d];
        __syncthreads();
    }
    if (t == 0) g_bsum[b] = sh[0];
}
// fused: block b computes its global base (sum of bsum[0..b)) + local scan
__global__ void writeoff_fused_kernel() {
    __shared__ int sh[256];
    __shared__ int red[256];
    int b = blockIdx.x, t = threadIdx.x;
    int i = b * 256 + t;

    int p = 0;
    for (int j = t; j < b; j += 256) p += g_bsum[j];
    red[t] = p;
    int dg = (i < N_NODES) ? g_deg[i] : 0;
    sh[t] = dg;
    __syncthreads();
    for (int d = 128; d > 0; d >>= 1) {
        if (t < d) red[t] += red[t + d];
        __syncthreads();
    }
    int base = red[0];
    // inclusive scan of degrees
    for (int d = 1; d < 256; d <<= 1) {
        int v = (t >= d) ? sh[t - d] : 0;
        __syncthreads();
        sh[t] += v;
        __syncthreads();
    }
    if (i < N_NODES) {
        int off = base + sh[t] - dg;
        g_off[i] = off;
        g_cur[i] = off;
        g_invdeg[i] = 1.0f / (float)(dg > 0 ? dg : 1);
        if (i == N_NODES - 1) g_off[N_NODES] = off + dg;
    }
}
__global__ void build_csr_kernel(const int* __restrict__ src,
                                 const int* __restrict__ dst) {
    int i = blockIdx.x * blockDim.x + threadIdx.x;
    if (i < N_EDGES) {
        int d = dst[i];
        int p = atomicAdd(&g_cur[d], 1);
        g_csr[p] = src[i];
    }
}

// ---------------- fp32 -> fp16 plane conversion ------------------------------
__global__ void to_f16_kernel(const float* __restrict__ in,
                              __half* __restrict__ out, int n4) {
    int i = blockIdx.x * blockDim.x + threadIdx.x;
    if (i < n4) {
        float4 v = *(const float4*)(in + (long long)i * 4);
        *(__half2*)(out + (long long)i * 4)     = __floats2half2_rn(v.x, v.y);
        *(__half2*)(out + (long long)i * 4 + 2) = __floats2half2_rn(v.z, v.w);
    }
}

// ---------------- gather-side mean aggregation (warp per node, fp16 src) -----
// MLP=8: 8 outstanding row loads per batch to cover L2 latency.
__global__ void gather_mean_f16_kernel(const __half* __restrict__ hsrc,
                                       float* __restrict__ out) {
    int warp = (blockIdx.x * blockDim.x + threadIdx.x) >> 5;
    if (warp >= N_NODES) return;
    int lane = threadIdx.x & 31;
    int s0 = g_off[warp];
    int s1 = g_off[warp + 1];
    float4 acc = make_float4(0.f, 0.f, 0.f, 0.f);

    auto addRow = [&](int node) {
        uint2 raw = *(const uint2*)(hsrc + (long long)node * DIM + lane * 4);
        __half2 p0 = *(__half2*)&raw.x;
        __half2 p1 = *(__half2*)&raw.y;
        float2 f0 = __half22float2(p0);
        float2 f1 = __half22float2(p1);
        acc.x += f0.x; acc.y += f0.y; acc.z += f1.x; acc.w += f1.y;
    };

    for (int e = s0; e < s1; e += 32) {
        int idx = (e + lane < s1) ? g_csr[e + lane] : 0;
        int cnt = s1 - e; if (cnt > 32) cnt = 32;
        int j = 0;
        for (; j + 8 <= cnt; j += 8) {
            int n0 = __shfl_sync(0xffffffffu, idx, j + 0);
            int n1 = __shfl_sync(0xffffffffu, idx, j + 1);
            int n2 = __shfl_sync(0xffffffffu, idx, j + 2);
            int n3 = __shfl_sync(0xffffffffu, idx, j + 3);
            int n4 = __shfl_sync(0xffffffffu, idx, j + 4);
            int n5 = __shfl_sync(0xffffffffu, idx, j + 5);
            int n6 = __shfl_sync(0xffffffffu, idx, j + 6);
            int n7 = __shfl_sync(0xffffffffu, idx, j + 7);
            uint2 r0 = *(const uint2*)(hsrc + (long long)n0 * DIM + lane * 4);
            uint2 r1 = *(const uint2*)(hsrc + (long long)n1 * DIM + lane * 4);
            uint2 r2 = *(const uint2*)(hsrc + (long long)n2 * DIM + lane * 4);
            uint2 r3 = *(const uint2*)(hsrc + (long long)n3 * DIM + lane * 4);
            uint2 r4 = *(const uint2*)(hsrc + (long long)n4 * DIM + lane * 4);
            uint2 r5 = *(const uint2*)(hsrc + (long long)n5 * DIM + lane * 4);
            uint2 r6 = *(const uint2*)(hsrc + (long long)n6 * DIM + lane * 4);
            uint2 r7 = *(const uint2*)(hsrc + (long long)n7 * DIM + lane * 4);
            uint2 rs[8] = {r0, r1, r2, r3, r4, r5, r6, r7};
#pragma unroll
            for (int q = 0; q < 8; q++) {
                float2 f0 = __half22float2(*(__half2*)&rs[q].x);
                float2 f1 = __half22float2(*(__half2*)&rs[q].y);
                acc.x += f0.x; acc.y += f0.y; acc.z += f1.x; acc.w += f1.y;
            }
        }
        for (; j < cnt; j++) addRow(__shfl_sync(0xffffffffu, idx, j));
    }
    float inv = g_invdeg[warp];
    float4 r = make_float4(acc.x * inv, acc.y * inv, acc.z * inv, acc.w * inv);
    *(float4*)(out + (long long)warp * DIM + lane * 4) = r;
}

// ---------------- persistent mma.sync bf16-split GEMM ------------------------
// out[M, NTILE] = act( [A1 | A2] @ [W1 ; W2] + bias|addin ); optional fp16 out.
// D = Ah*Wh + Ah*Wl + Al*Wh  (drop Al*Wl, rel err ~1.5e-5).
// Persistent: grid-stride over 128-row tiles; W staged once per CTA.

#define MMA_BF16(d, a, b)                                                     \
    asm volatile(                                                             \
        "mma.sync.aligned.m16n8k16.row.col.f32.bf16.bf16.f32 "                \
        "{%0,%1,%2,%3}, {%4,%5,%6,%7}, {%8,%9}, {%0,%1,%2,%3};"               \
        : "+f"((d)[0]), "+f"((d)[1]), "+f"((d)[2]), "+f"((d)[3])              \
        : "r"((a)[0]), "r"((a)[1]), "r"((a)[2]), "r"((a)[3]),                 \
          "r"((b)[0]), "r"((b)[1]))

#define LDSM_X4(r0, r1, r2, r3, addr)                                         \
    asm volatile("ldmatrix.sync.aligned.m8n8.x4.shared.b16 {%0,%1,%2,%3}, [%4];" \
        : "=r"(r0), "=r"(r1), "=r"(r2), "=r"(r3) : "r"(addr))

__device__ __forceinline__ uint32_t smem_u32(const void* p) {
    uint32_t a;
    asm("{ .reg .u64 t; cvta.to.shared.u64 t, %1; cvt.u32.u64 %0, t; }"
        : "=r"(a) : "l"(p));
    return a;
}

template <int KTOT, int NTILE, bool RELU, bool DUAL, bool WF16, bool ADDIN>
__global__ void __launch_bounds__(256, 1)
mma_gemm(const float* __restrict__ A1, const float* __restrict__ A2,
         const float* __restrict__ W1, const float* __restrict__ W2,
         const float* __restrict__ bias, const float* __restrict__ addin,
         float* __restrict__ out, __half* __restrict__ out16, int M) {
    constexpr int COLW = NTILE / 64;
    constexpr int ROWG = 8 / COLW;
    constexpr int RPW  = 128 / ROWG;
    constexpr int MF   = RPW / 16;
    constexpr int KC     = 64;
    constexpr int NCHUNK = KTOT / KC;
    constexpr int SA = KC + 8;
    constexpr int SB = KTOT + 8;

    extern __shared__ __align__(16) __nv_bfloat16 smem[];
    __nv_bfloat16* WH = smem;                        // [NTILE][SB]
    __nv_bfloat16* WL = WH + NTILE * SB;
    __nv_bfloat16* AH = WL + NTILE * SB;             // [2 stages][128][SA]
    __nv_bfloat16* AL = AH + 2 * 128 * SA;

    const uint32_t sbase = smem_u32(smem);
    const int tid  = threadIdx.x;
    const int wid  = tid >> 5;
    const int lane = tid & 31;
    const int g    = lane >> 2;
    const int tq   = lane & 3;
    const int l8   = lane & 7;
    const int sel  = lane >> 3;

    // --- stage W transposed [n][k], split hi/lo (ONCE per CTA) ---
    for (int idx = tid; idx < KTOT * NTILE; idx += 256) {
        int k = idx / NTILE, n = idx % NTILE;
        float w = (DUAL && k >= 128) ? W2[(k - 128) * NTILE + n]
                                     : W1[k * NTILE + n];
        __nv_bfloat16 h = __float2bfloat16(w);
        __nv_bfloat16 l = __float2bfloat16(w - __bfloat162float(h));
        WH[n * SB + k] = h;
        WL[n * SB + k] = l;
    }

    auto stageA = [&](int row0, int c, int s) {
        const float* base; int kb;
        if (DUAL && c >= 2) { base = A2; kb = (c - 2) * KC; }
        else                { base = A1; kb = c * KC; }
        __nv_bfloat16* ah = AH + s * 128 * SA;
        __nv_bfloat16* al = AL + s * 128 * SA;
#pragma unroll
        for (int it = 0; it < 8; it++) {
            int idx = tid + it * 256;
            int r = idx >> 4, q = idx & 15;
            int gr = row0 + r;
            float4 v = make_float4(0.f, 0.f, 0.f, 0.f);
            if (gr < M) v = *(const float4*)(base + (long long)gr * DIM + kb + q * 4);
            float f[4] = {v.x, v.y, v.z, v.w};
            unsigned long long hp = 0ull, lp = 0ull;
#pragma unroll
            for (int j = 0; j < 4; j++) {
                __nv_bfloat16 h = __float2bfloat16(f[j]);
                __nv_bfloat16 l = __float2bfloat16(f[j] - __bfloat162float(h));
                hp |= (unsigned long long)__bfloat16_as_ushort(h) << (16 * j);
                lp |= (unsigned long long)__bfloat16_as_ushort(l) << (16 * j);
            }
            *(unsigned long long*)(ah + r * SA + q * 4) = hp;
            *(unsigned long long*)(al + r * SA + q * 4) = lp;
        }
    };

    const int cw = wid % COLW;
    const int rw = wid / COLW;
    const int n0 = cw * 64;
    const int wr0 = rw * RPW;

    const int a_row_l = l8 + ((sel & 1) << 3);
    const int a_kadd  = (sel >> 1) << 3;
    const int b_row_l = l8 + ((sel >> 1) << 3);
    const int b_kadd  = (sel & 1) << 3;

    const uint32_t whB = sbase;
    const uint32_t wlB = sbase + (uint32_t)(NTILE * SB) * 2;
    const uint32_t ahB = wlB + (uint32_t)(NTILE * SB) * 2;
    const uint32_t alB = ahB + (uint32_t)(2 * 128 * SA) * 2;

    const int NT = (M + 127) >> 7;
    __syncthreads();   // W staged before first tile's compute

    for (int tile = blockIdx.x; tile < NT; tile += gridDim.x) {
        const int row0 = tile << 7;

        float acc[MF][8][4];
#pragma unroll
        for (int mf = 0; mf < MF; mf++)
#pragma unroll
            for (int nf = 0; nf < 8; nf++)
#pragma unroll
                for (int j = 0; j < 4; j++) acc[mf][nf][j] = 0.f;

        stageA(row0, 0, 0);
        __syncthreads();

#pragma unroll 1
        for (int c = 0; c < NCHUNK; c++) {
            if (c + 1 < NCHUNK) stageA(row0, c + 1, (c + 1) & 1);

            const uint32_t ast = (uint32_t)((c & 1) * 128 * SA) * 2;
#pragma unroll
            for (int ks = 0; ks < KC / 16; ks++) {
                const int k0 = ks * 16;
                const int kg = c * KC + k0;

                uint32_t afh[MF][4], afl[MF][4];
#pragma unroll
                for (int mf = 0; mf < MF; mf++) {
                    uint32_t ao = (uint32_t)((wr0 + mf * 16 + a_row_l) * SA
                                             + k0 + a_kadd) * 2;
                    LDSM_X4(afh[mf][0], afh[mf][1], afh[mf][2], afh[mf][3],
                            ahB + ast + ao);
                    LDSM_X4(afl[mf][0], afl[mf][1], afl[mf][2], afl[mf][3],
                            alB + ast + ao);
                }
                uint32_t bh[8][2], bl[8][2];
#pragma unroll
                for (int nfp = 0; nfp < 4; nfp++) {
                    uint32_t bo = (uint32_t)((n0 + nfp * 16 + b_row_l) * SB
                                             + kg + b_kadd) * 2;
                    LDSM_X4(bh[2 * nfp][0], bh[2 * nfp][1],
                            bh[2 * nfp + 1][0], bh[2 * nfp + 1][1], whB + bo);
                    LDSM_X4(bl[2 * nfp][0], bl[2 * nfp][1],
                            bl[2 * nfp + 1][0], bl[2 * nfp + 1][1], wlB + bo);
                }
#pragma unroll
                for (int nf = 0; nf < 8; nf++)
#pragma unroll
                    for (int mf = 0; mf < MF; mf++) {
                        MMA_BF16(acc[mf][nf], afh[mf], bh[nf]);
                        MMA_BF16(acc[mf][nf], afh[mf], bl[nf]);
                        MMA_BF16(acc[mf][nf], afl[mf], bh[nf]);
                    }
            }
            __syncthreads();
        }

        // --- epilogue: bias or addin, (+relu), optional fp16 plane, store ---
#pragma unroll
        for (int mf = 0; mf < MF; mf++) {
#pragma unroll
            for (int nf = 0; nf < 8; nf++) {
                int col = n0 + nf * 8 + 2 * tq;
                int r = row0 + wr0 + mf * 16 + g;
                float a00, a01, a10, a11;
                if (ADDIN) {
                    float2 t0 = (r < M)
                        ? *(const float2*)(addin + (long long)r * NTILE + col)
                        : make_float2(0.f, 0.f);
                    float2 t1 = (r + 8 < M)
                        ? *(const float2*)(addin + (long long)(r + 8) * NTILE + col)
                        : make_float2(0.f, 0.f);
                    a00 = t0.x; a01 = t0.y; a10 = t1.x; a11 = t1.y;
                } else {
                    a00 = __ldg(&bias[col]); a01 = __ldg(&bias[col + 1]);
                    a10 = a00; a11 = a01;
                }
                float v0 = acc[mf][nf][0] + a00, v1 = acc[mf][nf][1] + a01;
                float v2 = acc[mf][nf][2] + a10, v3 = acc[mf][nf][3] + a11;
                if (RELU) {
                    v0 = fmaxf(v0, 0.f); v1 = fmaxf(v1, 0.f);
                    v2 = fmaxf(v2, 0.f); v3 = fmaxf(v3, 0.f);
                }
                if (r < M) {
                    *(float2*)(out + (long long)r * NTILE + col) = make_float2(v0, v1);
                    if (WF16)
                        *(__half2*)(out16 + (long long)r * NTILE + col) =
                            __floats2half2_rn(v0, v1);
                }
                if (r + 8 < M) {
                    *(float2*)(out + (long long)(r + 8) * NTILE + col) = make_float2(v2, v3);
                    if (WF16)
                        *(__half2*)(out16 + (long long)(r + 8) * NTILE + col) =
                            __floats2half2_rn(v2, v3);
                }
            }
        }
    }
}

// ---------------- launch ------------------------------------------------------
extern "C" void kernel_launch(void* const* d_in, const int* in_sizes, int n_in,
                              void* d_out, int out_size) {
    (void)in_sizes; (void)n_in; (void)out_size;
    const float* features = (const float*)d_in[0];
    const int*   src      = (const int*)  d_in[1];
    const int*   dst      = (const int*)  d_in[2];
    const float* W_self1  = (const float*)d_in[3];
    const float* W_neigh1 = (const float*)d_in[4];
    const float* b1       = (const float*)d_in[5];
    const float* W_self2  = (const float*)d_in[6];
    const float* W_neigh2 = (const float*)d_in[7];
    const float* b2       = (const float*)d_in[8];
    const float* W_out    = (const float*)d_in[9];
    const float* b_out    = (const float*)d_in[10];
    float*       out      = (float*)d_out;

    float *agg, *h1, *h2; __half* p16; int* degp;
    cudaGetSymbolAddress((void**)&agg, g_agg);
    cudaGetSymbolAddress((void**)&h1,  g_h1);
    cudaGetSymbolAddress((void**)&h2,  g_h2);
    cudaGetSymbolAddress((void**)&p16, g_p16);
    cudaGetSymbolAddress((void**)&degp, g_deg);

    const int SMEM_L2 = (2 * 128 * (256 + 8) + 4 * 128 * 72) * 2;  // 208896
    const int SMEM_L1 = (2 * 128 * (128 + 8) + 4 * 128 * 72) * 2;  // 143360
    const int SMEM_O  = (2 * 64  * (128 + 8) + 4 * 128 * 72) * 2;  // 108544
    cudaFuncSetAttribute(mma_gemm<128, 128, false, false, false, false>,
                         cudaFuncAttributeMaxDynamicSharedMemorySize, SMEM_L1);
    cudaFuncSetAttribute(mma_gemm<128, 128, true, false, true, true>,
                         cudaFuncAttributeMaxDynamicSharedMemorySize, SMEM_L1);
    cudaFuncSetAttribute(mma_gemm<256, 128, true, true, false, false>,
                         cudaFuncAttributeMaxDynamicSharedMemorySize, SMEM_L2);
    cudaFuncSetAttribute(mma_gemm<128, 64, false, false, false, false>,
                         cudaFuncAttributeMaxDynamicSharedMemorySize, SMEM_O);

    const int EB = (N_EDGES + 255) / 256;          // 6250
    const int NB = (N_NODES + 255) / 256;          // 391
    const int GB = (N_NODES * 32 + 255) / 256;     // 12500 (warp per node)
    const int CB = (N_NODES * DIM / 4 + 255) / 256;
    const int PG = 148;                            // persistent GEMM grid

    // 0) zero degrees (memset node, not a kernel launch)
    cudaMemsetAsync(degp, 0, N_NODES * sizeof(int));

    // 1-3) CSR head + fp16 plane
    count_deg_kernel<<<EB, 256>>>(dst);
    to_f16_kernel<<<CB, 256>>>(features, p16, N_NODES * DIM / 4);
    degsum_kernel<<<NB, 256>>>();

    // 4) layer-1 self GEMM (CSR-independent) — lands in the profiled slot
    mma_gemm<128, 128, false, false, false, false><<<PG, 256, SMEM_L1>>>(
        features, nullptr, W_self1, nullptr, b1, nullptr, h1, nullptr, N_NODES);

    // 5-6) CSR tail
    writeoff_fused_kernel<<<NB, 256>>>();
    build_csr_kernel<<<EB, 256>>>(src, dst);

    // 7-8) layer 1: gather + neigh GEMM (adds self partial, relu, fp16 plane)
    gather_mean_f16_kernel<<<GB, 256>>>(p16, agg);
    mma_gemm<128, 128, true, false, true, true><<<PG, 256, SMEM_L1>>>(
        agg, nullptr, W_neigh1, nullptr, nullptr, h1, h1, p16, N_NODES);

    // 9-10) layer 2 (fused dual K=256)
    gather_mean_f16_kernel<<<GB, 256>>>(p16, agg);
    mma_gemm<256, 128, true, true, false, false><<<PG, 256, SMEM_L2>>>(
        h1, agg, W_self2, W_neigh2, b2, nullptr, h2, nullptr, N_NODES);

    // 11) output projection (2 CTAs/SM fit at 108.5 KB)
    mma_gemm<128, 64, false, false, false, false><<<296, 256, SMEM_O>>>(
        h2, nullptr, W_out, nullptr, b_out, nullptr, out, nullptr, N_NODES);
}

// round 9
// speedup vs baseline: 2.3055x; 1.1105x over previous
#include <cuda_runtime.h>
#include <cuda_bf16.h>
#include <cuda_fp16.h>
#include <cstdint>

#define N_NODES 100000
#define N_EDGES 1600000
#define DIM     128

// ---------------- scratch (device globals; no allocation in kernel_launch) ---
__device__ int   g_deg[N_NODES];
__device__ int   g_off[N_NODES + 1];
__device__ int   g_cur[N_NODES];
__device__ int   g_csr[N_EDGES];
__device__ float g_invdeg[N_NODES];
__device__ int   g_bsum[512];
// bf16 hi/lo plane pairs (pre-split GEMM A operands)
__device__ __nv_bfloat16 g_fh [(long long)N_NODES * DIM];
__device__ __nv_bfloat16 g_fl [(long long)N_NODES * DIM];
__device__ __nv_bfloat16 g_gh [(long long)N_NODES * DIM];
__device__ __nv_bfloat16 g_gl [(long long)N_NODES * DIM];
__device__ __nv_bfloat16 g_h1h[(long long)N_NODES * DIM];
__device__ __nv_bfloat16 g_h1l[(long long)N_NODES * DIM];
__device__ __nv_bfloat16 g_h2h[(long long)N_NODES * DIM];
__device__ __nv_bfloat16 g_h2l[(long long)N_NODES * DIM];
__device__ __half g_p16[(long long)N_NODES * DIM];   // fp16 gather plane

// ---------------- CSR build --------------------------------------------------
__global__ void count_deg_kernel(const int* __restrict__ dst) {
    int i = blockIdx.x * blockDim.x + threadIdx.x;
    if (i < N_EDGES) atomicAdd(&g_deg[dst[i]], 1);
}
__global__ void degsum_kernel() {
    __shared__ int sh[256];
    int b = blockIdx.x, t = threadIdx.x;
    int i = b * 256 + t;
    sh[t] = (i < N_NODES) ? g_deg[i] : 0;
    __syncthreads();
    for (int d = 128; d > 0; d >>= 1) {
        if (t < d) sh[t] += sh[t + d];
        __syncthreads();
    }
    if (t == 0) g_bsum[b] = sh[0];
}
__global__ void writeoff_fused_kernel() {
    __shared__ int sh[256];
    __shared__ int red[256];
    int b = blockIdx.x, t = threadIdx.x;
    int i = b * 256 + t;
    int p = 0;
    for (int j = t; j < b; j += 256) p += g_bsum[j];
    red[t] = p;
    int dg = (i < N_NODES) ? g_deg[i] : 0;
    sh[t] = dg;
    __syncthreads();
    for (int d = 128; d > 0; d >>= 1) {
        if (t < d) red[t] += red[t + d];
        __syncthreads();
    }
    int base = red[0];
    for (int d = 1; d < 256; d <<= 1) {
        int v = (t >= d) ? sh[t - d] : 0;
        __syncthreads();
        sh[t] += v;
        __syncthreads();
    }
    if (i < N_NODES) {
        int off = base + sh[t] - dg;
        g_off[i] = off;
        g_cur[i] = off;
        g_invdeg[i] = 1.0f / (float)(dg > 0 ? dg : 1);
        if (i == N_NODES - 1) g_off[N_NODES] = off + dg;
    }
}
__global__ void build_csr_kernel(const int* __restrict__ src,
                                 const int* __restrict__ dst) {
    int i = blockIdx.x * blockDim.x + threadIdx.x;
    if (i < N_EDGES) {
        int d = dst[i];
        int p = atomicAdd(&g_cur[d], 1);
        g_csr[p] = src[i];
    }
}

// ---------------- prep: features -> bf16 hi/lo planes + fp16 plane ----------
__global__ void prep_kernel(const float* __restrict__ in, int n4) {
    int i = blockIdx.x * blockDim.x + threadIdx.x;
    if (i >= n4) return;
    float4 v = *(const float4*)(in + (long long)i * 4);
    float f[4] = {v.x, v.y, v.z, v.w};
    __nv_bfloat162 h01, h23, l01, l23;
    __nv_bfloat16 h0 = __float2bfloat16(f[0]);
    __nv_bfloat16 h1 = __float2bfloat16(f[1]);
    __nv_bfloat16 h2 = __float2bfloat16(f[2]);
    __nv_bfloat16 h3 = __float2bfloat16(f[3]);
    h01.x = h0; h01.y = h1; h23.x = h2; h23.y = h3;
    l01.x = __float2bfloat16(f[0] - __bfloat162float(h0));
    l01.y = __float2bfloat16(f[1] - __bfloat162float(h1));
    l23.x = __float2bfloat16(f[2] - __bfloat162float(h2));
    l23.y = __float2bfloat16(f[3] - __bfloat162float(h3));
    *(__nv_bfloat162*)(g_fh + (long long)i * 4)     = h01;
    *(__nv_bfloat162*)(g_fh + (long long)i * 4 + 2) = h23;
    *(__nv_bfloat162*)(g_fl + (long long)i * 4)     = l01;
    *(__nv_bfloat162*)(g_fl + (long long)i * 4 + 2) = l23;
    *(__half2*)(g_p16 + (long long)i * 4)     = __floats2half2_rn(f[0], f[1]);
    *(__half2*)(g_p16 + (long long)i * 4 + 2) = __floats2half2_rn(f[2], f[3]);
}

// ---------------- gather-side mean aggregation (warp per node, fp16 src) -----
// Writes agg directly as bf16 hi/lo planes.
__global__ void gather_mean_f16_kernel(const __half* __restrict__ hsrc) {
    int warp = (blockIdx.x * blockDim.x + threadIdx.x) >> 5;
    if (warp >= N_NODES) return;
    int lane = threadIdx.x & 31;
    int s0 = g_off[warp];
    int s1 = g_off[warp + 1];
    float4 acc = make_float4(0.f, 0.f, 0.f, 0.f);

    auto addRow = [&](int node) {
        uint2 raw = *(const uint2*)(hsrc + (long long)node * DIM + lane * 4);
        float2 f0 = __half22float2(*(__half2*)&raw.x);
        float2 f1 = __half22float2(*(__half2*)&raw.y);
        acc.x += f0.x; acc.y += f0.y; acc.z += f1.x; acc.w += f1.y;
    };

    for (int e = s0; e < s1; e += 32) {
        int idx = (e + lane < s1) ? g_csr[e + lane] : 0;
        int cnt = s1 - e; if (cnt > 32) cnt = 32;
        int j = 0;
        for (; j + 8 <= cnt; j += 8) {
            int n0 = __shfl_sync(0xffffffffu, idx, j + 0);
            int n1 = __shfl_sync(0xffffffffu, idx, j + 1);
            int n2 = __shfl_sync(0xffffffffu, idx, j + 2);
            int n3 = __shfl_sync(0xffffffffu, idx, j + 3);
            int n4 = __shfl_sync(0xffffffffu, idx, j + 4);
            int n5 = __shfl_sync(0xffffffffu, idx, j + 5);
            int n6 = __shfl_sync(0xffffffffu, idx, j + 6);
            int n7 = __shfl_sync(0xffffffffu, idx, j + 7);
            uint2 r0 = *(const uint2*)(hsrc + (long long)n0 * DIM + lane * 4);
            uint2 r1 = *(const uint2*)(hsrc + (long long)n1 * DIM + lane * 4);
            uint2 r2 = *(const uint2*)(hsrc + (long long)n2 * DIM + lane * 4);
            uint2 r3 = *(const uint2*)(hsrc + (long long)n3 * DIM + lane * 4);
            uint2 r4 = *(const uint2*)(hsrc + (long long)n4 * DIM + lane * 4);
            uint2 r5 = *(const uint2*)(hsrc + (long long)n5 * DIM + lane * 4);
            uint2 r6 = *(const uint2*)(hsrc + (long long)n6 * DIM + lane * 4);
            uint2 r7 = *(const uint2*)(hsrc + (long long)n7 * DIM + lane * 4);
            uint2 rs[8] = {r0, r1, r2, r3, r4, r5, r6, r7};
#pragma unroll
            for (int q = 0; q < 8; q++) {
                float2 f0 = __half22float2(*(__half2*)&rs[q].x);
                float2 f1 = __half22float2(*(__half2*)&rs[q].y);
                acc.x += f0.x; acc.y += f0.y; acc.z += f1.x; acc.w += f1.y;
            }
        }
        for (; j < cnt; j++) addRow(__shfl_sync(0xffffffffu, idx, j));
    }
    float inv = g_invdeg[warp];
    float f[4] = {acc.x * inv, acc.y * inv, acc.z * inv, acc.w * inv};
    long long o = (long long)warp * DIM + lane * 4;
    __nv_bfloat162 h01, h23, l01, l23;
    __nv_bfloat16 h0 = __float2bfloat16(f[0]);
    __nv_bfloat16 h1 = __float2bfloat16(f[1]);
    __nv_bfloat16 h2 = __float2bfloat16(f[2]);
    __nv_bfloat16 h3 = __float2bfloat16(f[3]);
    h01.x = h0; h01.y = h1; h23.x = h2; h23.y = h3;
    l01.x = __float2bfloat16(f[0] - __bfloat162float(h0));
    l01.y = __float2bfloat16(f[1] - __bfloat162float(h1));
    l23.x = __float2bfloat16(f[2] - __bfloat162float(h2));
    l23.y = __float2bfloat16(f[3] - __bfloat162float(h3));
    *(__nv_bfloat162*)(g_gh + o)     = h01;
    *(__nv_bfloat162*)(g_gh + o + 2) = h23;
    *(__nv_bfloat162*)(g_gl + o)     = l01;
    *(__nv_bfloat162*)(g_gl + o + 2) = l23;
}

// ---------------- persistent mma.sync bf16-split GEMM (cp.async staged) ------
// D = Ah*Wh + Ah*Wl + Al*Wh over pre-split bf16 planes. W staged once per CTA.

#define MMA_BF16(d, a, b)                                                     \
    asm volatile(                                                             \
        "mma.sync.aligned.m16n8k16.row.col.f32.bf16.bf16.f32 "                \
        "{%0,%1,%2,%3}, {%4,%5,%6,%7}, {%8,%9}, {%0,%1,%2,%3};"               \
        : "+f"((d)[0]), "+f"((d)[1]), "+f"((d)[2]), "+f"((d)[3])              \
        : "r"((a)[0]), "r"((a)[1]), "r"((a)[2]), "r"((a)[3]),                 \
          "r"((b)[0]), "r"((b)[1]))

#define LDSM_X4(r0, r1, r2, r3, addr)                                         \
    asm volatile("ldmatrix.sync.aligned.m8n8.x4.shared.b16 {%0,%1,%2,%3}, [%4];" \
        : "=r"(r0), "=r"(r1), "=r"(r2), "=r"(r3) : "r"(addr))

#define CP_ASYNC16(dst, src)                                                  \
    asm volatile("cp.async.cg.shared.global [%0], [%1], 16;"                  \
                 :: "r"(dst), "l"(src))
#define CP_COMMIT()  asm volatile("cp.async.commit_group;" ::: "memory")
#define CP_WAIT(n)   asm volatile("cp.async.wait_group %0;" :: "n"(n) : "memory")

__device__ __forceinline__ uint32_t smem_u32(const void* p) {
    uint32_t a;
    asm("{ .reg .u64 t; cvta.to.shared.u64 t, %1; cvt.u32.u64 %0, t; }"
        : "=r"(a) : "l"(p));
    return a;
}

template <int KTOT, int NTILE, bool RELU, bool DUAL, bool WPL, bool WF16, bool WF32>
__global__ void __launch_bounds__(256, 1)
mma_gemm(const __nv_bfloat16* __restrict__ A1H, const __nv_bfloat16* __restrict__ A1L,
         const __nv_bfloat16* __restrict__ A2H, const __nv_bfloat16* __restrict__ A2L,
         const float* __restrict__ W1, const float* __restrict__ W2,
         const float* __restrict__ bias,
         __nv_bfloat16* __restrict__ outH, __nv_bfloat16* __restrict__ outL,
         __half* __restrict__ out16, float* __restrict__ outF, int M) {
    constexpr int COLW = NTILE / 64;
    constexpr int ROWG = 8 / COLW;
    constexpr int RPW  = 128 / ROWG;
    constexpr int MF   = RPW / 16;
    constexpr int KC     = 64;
    constexpr int NCHUNK = KTOT / KC;
    constexpr int SA = KC + 8;
    constexpr int SB = KTOT + 8;
    constexpr int ABYTES = 128 * SA * 2;   // one stage, one plane

    extern __shared__ __align__(16) __nv_bfloat16 smem[];
    __nv_bfloat16* WH = smem;                        // [NTILE][SB]
    __nv_bfloat16* WL = WH + NTILE * SB;

    const uint32_t sbase = smem_u32(smem);
    const int tid  = threadIdx.x;
    const int wid  = tid >> 5;
    const int lane = tid & 31;
    const int g    = lane >> 2;
    const int tq   = lane & 3;
    const int l8   = lane & 7;
    const int sel  = lane >> 3;

    // --- stage W transposed [n][k], split hi/lo (once per CTA) ---
    for (int idx = tid; idx < KTOT * NTILE; idx += 256) {
        int k = idx / NTILE, n = idx % NTILE;
        float w = (DUAL && k >= 128) ? W2[(k - 128) * NTILE + n]
                                     : W1[k * NTILE + n];
        __nv_bfloat16 h = __float2bfloat16(w);
        WH[n * SB + k] = h;
        WL[n * SB + k] = __float2bfloat16(w - __bfloat162float(h));
    }

    const uint32_t whB = sbase;
    const uint32_t wlB = sbase + (uint32_t)(NTILE * SB) * 2;
    const uint32_t ahB = wlB + (uint32_t)(NTILE * SB) * 2;   // [2 stages][128][SA]
    const uint32_t alB = ahB + 2 * ABYTES;                   // [2 stages][128][SA]

    // --- async A staging: 2048 x 16B per chunk (hi+lo planes) ---
    auto stageA = [&](int row0, int c, int s) {
        const __nv_bfloat16 *ph, *pl; int kb;
        if (DUAL && c >= NCHUNK / 2) { ph = A2H; pl = A2L; kb = (c - NCHUNK / 2) * KC; }
        else                         { ph = A1H; pl = A1L; kb = c * KC; }
        const uint32_t ahD = ahB + (uint32_t)s * ABYTES;
        const uint32_t alD = alB + (uint32_t)s * ABYTES;
#pragma unroll
        for (int it = 0; it < 8; it++) {
            int idx = tid + it * 256;            // 0..2047
            int plane = idx >> 10;
            int rem = idx & 1023;
            int r = rem >> 3, q = rem & 7;
            long long gr = row0 + r;
            if (gr > M - 1) gr = M - 1;          // clamp (rows >= M never stored)
            const __nv_bfloat16* src = (plane ? pl : ph) + gr * DIM + kb + q * 8;
            uint32_t dst = (plane ? alD : ahD) + (uint32_t)(r * SA + q * 8) * 2;
            CP_ASYNC16(dst, src);
        }
        CP_COMMIT();
    };

    const int cw = wid % COLW;
    const int rw = wid / COLW;
    const int n0 = cw * 64;
    const int wr0 = rw * RPW;

    const int a_row_l = l8 + ((sel & 1) << 3);
    const int a_kadd  = (sel >> 1) << 3;
    const int b_row_l = l8 + ((sel >> 1) << 3);
    const int b_kadd  = (sel & 1) << 3;

    const int NT = (M + 127) >> 7;
    __syncthreads();   // W visible before first MMA

    for (int tile = blockIdx.x; tile < NT; tile += gridDim.x) {
        const int row0 = tile << 7;

        float acc[MF][8][4];
#pragma unroll
        for (int mf = 0; mf < MF; mf++)
#pragma unroll
            for (int nf = 0; nf < 8; nf++)
#pragma unroll
                for (int j = 0; j < 4; j++) acc[mf][nf][j] = 0.f;

        stageA(row0, 0, 0);

#pragma unroll 1
        for (int c = 0; c < NCHUNK; c++) {
            if (c + 1 < NCHUNK) { stageA(row0, c + 1, (c + 1) & 1); CP_WAIT(1); }
            else                { CP_WAIT(0); }
            __syncthreads();

            const uint32_t ast = (uint32_t)((c & 1)) * ABYTES;
#pragma unroll
            for (int ks = 0; ks < KC / 16; ks++) {
                const int k0 = ks * 16;
                const int kg = c * KC + k0;

                uint32_t afh[MF][4], afl[MF][4];
#pragma unroll
                for (int mf = 0; mf < MF; mf++) {
                    uint32_t ao = (uint32_t)((wr0 + mf * 16 + a_row_l) * SA
                                             + k0 + a_kadd) * 2;
                    LDSM_X4(afh[mf][0], afh[mf][1], afh[mf][2], afh[mf][3],
                            ahB + ast + ao);
                    LDSM_X4(afl[mf][0], afl[mf][1], afl[mf][2], afl[mf][3],
                            alB + ast + ao);
                }
                uint32_t bh[8][2], bl[8][2];
#pragma unroll
                for (int nfp = 0; nfp < 4; nfp++) {
                    uint32_t bo = (uint32_t)((n0 + nfp * 16 + b_row_l) * SB
                                             + kg + b_kadd) * 2;
                    LDSM_X4(bh[2 * nfp][0], bh[2 * nfp][1],
                            bh[2 * nfp + 1][0], bh[2 * nfp + 1][1], whB + bo);
                    LDSM_X4(bl[2 * nfp][0], bl[2 * nfp][1],
                            bl[2 * nfp + 1][0], bl[2 * nfp + 1][1], wlB + bo);
                }
#pragma unroll
                for (int nf = 0; nf < 8; nf++)
#pragma unroll
                    for (int mf = 0; mf < MF; mf++) {
                        MMA_BF16(acc[mf][nf], afh[mf], bh[nf]);
                        MMA_BF16(acc[mf][nf], afh[mf], bl[nf]);
                        MMA_BF16(acc[mf][nf], afl[mf], bh[nf]);
                    }
            }
            __syncthreads();   // all reads done before next stage overwrites
        }

        // --- epilogue: bias (+relu), plane/fp16/fp32 stores ---
#pragma unroll
        for (int mf = 0; mf < MF; mf++) {
#pragma unroll
            for (int nf = 0; nf < 8; nf++) {
                int col = n0 + nf * 8 + 2 * tq;
                int r = row0 + wr0 + mf * 16 + g;
                float b0 = __ldg(&bias[col]);
                float b1 = __ldg(&bias[col + 1]);
                float v[2][2] = {{acc[mf][nf][0] + b0, acc[mf][nf][1] + b1},
                                 {acc[mf][nf][2] + b0, acc[mf][nf][3] + b1}};
#pragma unroll
                for (int hrow = 0; hrow < 2; hrow++) {
                    int rr = r + hrow * 8;
                    if (rr >= M) continue;
                    float v0 = v[hrow][0], v1 = v[hrow][1];
                    if (RELU) { v0 = fmaxf(v0, 0.f); v1 = fmaxf(v1, 0.f); }
                    long long o = (long long)rr * NTILE + col;
                    if (WPL) {
                        __nv_bfloat162 hh, ll;
                        hh.x = __float2bfloat16(v0);
                        hh.y = __float2bfloat16(v1);
                        ll.x = __float2bfloat16(v0 - __bfloat162float(hh.x));
                        ll.y = __float2bfloat16(v1 - __bfloat162float(hh.y));
                        *(__nv_bfloat162*)(outH + o) = hh;
                        *(__nv_bfloat162*)(outL + o) = ll;
                    }
                    if (WF16)
                        *(__half2*)(out16 + o) = __floats2half2_rn(v0, v1);
                    if (WF32)
                        *(float2*)(outF + o) = make_float2(v0, v1);
                }
            }
        }
    }
}

// ---------------- launch ------------------------------------------------------
extern "C" void kernel_launch(void* const* d_in, const int* in_sizes, int n_in,
                              void* d_out, int out_size) {
    (void)in_sizes; (void)n_in; (void)out_size;
    const float* features = (const float*)d_in[0];
    const int*   src      = (const int*)  d_in[1];
    const int*   dst      = (const int*)  d_in[2];
    const float* W_self1  = (const float*)d_in[3];
    const float* W_neigh1 = (const float*)d_in[4];
    const float* b1       = (const float*)d_in[5];
    const float* W_self2  = (const float*)d_in[6];
    const float* W_neigh2 = (const float*)d_in[7];
    const float* b2       = (const float*)d_in[8];
    const float* W_out    = (const float*)d_in[9];
    const float* b_out    = (const float*)d_in[10];
    float*       out      = (float*)d_out;

    __nv_bfloat16 *fh, *fl, *gh, *gl, *h1h, *h1l, *h2h, *h2l;
    __half* p16; int* degp;
    cudaGetSymbolAddress((void**)&fh,  g_fh);
    cudaGetSymbolAddress((void**)&fl,  g_fl);
    cudaGetSymbolAddress((void**)&gh,  g_gh);
    cudaGetSymbolAddress((void**)&gl,  g_gl);
    cudaGetSymbolAddress((void**)&h1h, g_h1h);
    cudaGetSymbolAddress((void**)&h1l, g_h1l);
    cudaGetSymbolAddress((void**)&h2h, g_h2h);
    cudaGetSymbolAddress((void**)&h2l, g_h2l);
    cudaGetSymbolAddress((void**)&p16, g_p16);
    cudaGetSymbolAddress((void**)&degp, g_deg);

    const int SMEM_L = (2 * 128 * (256 + 8) + 4 * 128 * 72) * 2;  // 208896
    const int SMEM_O = (2 * 64  * (128 + 8) + 4 * 128 * 72) * 2;  // 108544
    cudaFuncSetAttribute(mma_gemm<256, 128, true, true, true, true, false>,
                         cudaFuncAttributeMaxDynamicSharedMemorySize, SMEM_L);
    cudaFuncSetAttribute(mma_gemm<256, 128, true, true, true, false, false>,
                         cudaFuncAttributeMaxDynamicSharedMemorySize, SMEM_L);
    cudaFuncSetAttribute(mma_gemm<128, 64, false, false, false, false, true>,
                         cudaFuncAttributeMaxDynamicSharedMemorySize, SMEM_O);

    const int EB = (N_EDGES + 255) / 256;          // 6250
    const int NB = (N_NODES + 255) / 256;          // 391
    const int GB = (N_NODES * 32 + 255) / 256;     // 12500 (warp per node)
    const int CB = (N_NODES * DIM / 4 + 255) / 256;
    const int PG = 148;

    // 0) zero degrees
    cudaMemsetAsync(degp, 0, N_NODES * sizeof(int));

    // 1-5) CSR build + feature planes
    count_deg_kernel<<<EB, 256>>>(dst);
    prep_kernel<<<CB, 256>>>(features, N_NODES * DIM / 4);
    degsum_kernel<<<NB, 256>>>();
    writeoff_fused_kernel<<<NB, 256>>>();
    build_csr_kernel<<<EB, 256>>>(src, dst);

    // 6-7) layer 1: gather + dual GEMM (writes h1 planes + fp16 plane)
    gather_mean_f16_kernel<<<GB, 256>>>(p16);
    mma_gemm<256, 128, true, true, true, true, false><<<PG, 256, SMEM_L>>>(
        fh, fl, gh, gl, W_self1, W_neigh1, b1, h1h, h1l, p16, nullptr, N_NODES);

    // 8-9) layer 2: gather + dual GEMM (writes h2 planes)
    gather_mean_f16_kernel<<<GB, 256>>>(p16);
    mma_gemm<256, 128, true, true, true, false, false><<<PG, 256, SMEM_L>>>(
        h1h, h1l, gh, gl, W_self2, W_neigh2, b2, h2h, h2l, nullptr, nullptr, N_NODES);

    // 10) output projection -> fp32 d_out
    mma_gemm<128, 64, false, false, false, false, true><<<296, 256, SMEM_O>>>(
        h2h, h2l, nullptr, nullptr, W_out, nullptr, b_out,
        nullptr, nullptr, nullptr, out, N_NODES);
}

// round 11
// speedup vs baseline: 2.3535x; 1.0208x over previous
#include <cuda_runtime.h>
#include <cuda_bf16.h>
#include <cuda_fp16.h>
#include <cstdint>

#define N_NODES 100000
#define N_EDGES 1600000
#define DIM     128

// ---------------- scratch (device globals; no allocation in kernel_launch) ---
__device__ int   g_deg[N_NODES];
__device__ int   g_off[N_NODES + 1];
__device__ int   g_cur[N_NODES];
__device__ int   g_csr[N_EDGES];
__device__ float g_invdeg[N_NODES];
__device__ int   g_bsum[512];
// bf16 hi/lo plane pairs (pre-split GEMM A operands)
__device__ __nv_bfloat16 g_fh [(long long)N_NODES * DIM];
__device__ __nv_bfloat16 g_fl [(long long)N_NODES * DIM];
__device__ __nv_bfloat16 g_gh [(long long)N_NODES * DIM];
__device__ __nv_bfloat16 g_gl [(long long)N_NODES * DIM];
__device__ __nv_bfloat16 g_h1h[(long long)N_NODES * DIM];
__device__ __nv_bfloat16 g_h1l[(long long)N_NODES * DIM];
__device__ __nv_bfloat16 g_h2h[(long long)N_NODES * DIM];
__device__ __nv_bfloat16 g_h2l[(long long)N_NODES * DIM];
__device__ __half g_p16[(long long)N_NODES * DIM];   // fp16 gather plane

// ---------------- CSR build --------------------------------------------------
__global__ void count_deg_kernel(const int* __restrict__ dst) {
    int i = blockIdx.x * blockDim.x + threadIdx.x;
    if (i < N_EDGES) atomicAdd(&g_deg[dst[i]], 1);
}
__global__ void degsum_kernel() {
    __shared__ int sh[256];
    int b = blockIdx.x, t = threadIdx.x;
    int i = b * 256 + t;
    sh[t] = (i < N_NODES) ? g_deg[i] : 0;
    __syncthreads();
    for (int d = 128; d > 0; d >>= 1) {
        if (t < d) sh[t] += sh[t + d];
        __syncthreads();
    }
    if (t == 0) g_bsum[b] = sh[0];
}
__global__ void writeoff_fused_kernel() {
    __shared__ int sh[256];
    __shared__ int red[256];
    int b = blockIdx.x, t = threadIdx.x;
    int i = b * 256 + t;
    int p = 0;
    for (int j = t; j < b; j += 256) p += g_bsum[j];
    red[t] = p;
    int dg = (i < N_NODES) ? g_deg[i] : 0;
    sh[t] = dg;
    __syncthreads();
    for (int d = 128; d > 0; d >>= 1) {
        if (t < d) red[t] += red[t + d];
        __syncthreads();
    }
    int base = red[0];
    for (int d = 1; d < 256; d <<= 1) {
        int v = (t >= d) ? sh[t - d] : 0;
        __syncthreads();
        sh[t] += v;
        __syncthreads();
    }
    if (i < N_NODES) {
        int off = base + sh[t] - dg;
        g_off[i] = off;
        g_cur[i] = off;
        g_invdeg[i] = 1.0f / (float)(dg > 0 ? dg : 1);
        if (i == N_NODES - 1) g_off[N_NODES] = off + dg;
    }
}
__global__ void build_csr_kernel(const int* __restrict__ src,
                                 const int* __restrict__ dst) {
    int i = blockIdx.x * blockDim.x + threadIdx.x;
    if (i < N_EDGES) {
        int d = dst[i];
        int p = atomicAdd(&g_cur[d], 1);
        g_csr[p] = src[i];
    }
}

// ---------------- prep: features -> bf16 hi/lo planes + fp16 plane ----------
__global__ void prep_kernel(const float* __restrict__ in, int n4) {
    int i = blockIdx.x * blockDim.x + threadIdx.x;
    if (i >= n4) return;
    float4 v = *(const float4*)(in + (long long)i * 4);
    float f[4] = {v.x, v.y, v.z, v.w};
    __nv_bfloat162 h01, h23, l01, l23;
    __nv_bfloat16 h0 = __float2bfloat16(f[0]);
    __nv_bfloat16 h1 = __float2bfloat16(f[1]);
    __nv_bfloat16 h2 = __float2bfloat16(f[2]);
    __nv_bfloat16 h3 = __float2bfloat16(f[3]);
    h01.x = h0; h01.y = h1; h23.x = h2; h23.y = h3;
    l01.x = __float2bfloat16(f[0] - __bfloat162float(h0));
    l01.y = __float2bfloat16(f[1] - __bfloat162float(h1));
    l23.x = __float2bfloat16(f[2] - __bfloat162float(h2));
    l23.y = __float2bfloat16(f[3] - __bfloat162float(h3));
    *(__nv_bfloat162*)(g_fh + (long long)i * 4)     = h01;
    *(__nv_bfloat162*)(g_fh + (long long)i * 4 + 2) = h23;
    *(__nv_bfloat162*)(g_fl + (long long)i * 4)     = l01;
    *(__nv_bfloat162*)(g_fl + (long long)i * 4 + 2) = l23;
    *(__half2*)(g_p16 + (long long)i * 4)     = __floats2half2_rn(f[0], f[1]);
    *(__half2*)(g_p16 + (long long)i * 4 + 2) = __floats2half2_rn(f[2], f[3]);
}

// ---------------- gather-side mean aggregation (warp per node, fp16 src) -----
__global__ void gather_mean_f16_kernel(const __half* __restrict__ hsrc) {
    int warp = (blockIdx.x * blockDim.x + threadIdx.x) >> 5;
    if (warp >= N_NODES) return;
    int lane = threadIdx.x & 31;
    int s0 = g_off[warp];
    int s1 = g_off[warp + 1];
    float4 acc = make_float4(0.f, 0.f, 0.f, 0.f);

    auto addRow = [&](int node) {
        uint2 raw = *(const uint2*)(hsrc + (long long)node * DIM + lane * 4);
        float2 f0 = __half22float2(*(__half2*)&raw.x);
        float2 f1 = __half22float2(*(__half2*)&raw.y);
        acc.x += f0.x; acc.y += f0.y; acc.z += f1.x; acc.w += f1.y;
    };

    for (int e = s0; e < s1; e += 32) {
        int idx = (e + lane < s1) ? g_csr[e + lane] : 0;
        int cnt = s1 - e; if (cnt > 32) cnt = 32;
        int j = 0;
        for (; j + 8 <= cnt; j += 8) {
            int n0 = __shfl_sync(0xffffffffu, idx, j + 0);
            int n1 = __shfl_sync(0xffffffffu, idx, j + 1);
            int n2 = __shfl_sync(0xffffffffu, idx, j + 2);
            int n3 = __shfl_sync(0xffffffffu, idx, j + 3);
            int n4 = __shfl_sync(0xffffffffu, idx, j + 4);
            int n5 = __shfl_sync(0xffffffffu, idx, j + 5);
            int n6 = __shfl_sync(0xffffffffu, idx, j + 6);
            int n7 = __shfl_sync(0xffffffffu, idx, j + 7);
            uint2 r0 = *(const uint2*)(hsrc + (long long)n0 * DIM + lane * 4);
            uint2 r1 = *(const uint2*)(hsrc + (long long)n1 * DIM + lane * 4);
            uint2 r2 = *(const uint2*)(hsrc + (long long)n2 * DIM + lane * 4);
            uint2 r3 = *(const uint2*)(hsrc + (long long)n3 * DIM + lane * 4);
            uint2 r4 = *(const uint2*)(hsrc + (long long)n4 * DIM + lane * 4);
            uint2 r5 = *(const uint2*)(hsrc + (long long)n5 * DIM + lane * 4);
            uint2 r6 = *(const uint2*)(hsrc + (long long)n6 * DIM + lane * 4);
            uint2 r7 = *(const uint2*)(hsrc + (long long)n7 * DIM + lane * 4);
            uint2 rs[8] = {r0, r1, r2, r3, r4, r5, r6, r7};
#pragma unroll
            for (int q = 0; q < 8; q++) {
                float2 f0 = __half22float2(*(__half2*)&rs[q].x);
                float2 f1 = __half22float2(*(__half2*)&rs[q].y);
                acc.x += f0.x; acc.y += f0.y; acc.z += f1.x; acc.w += f1.y;
            }
        }
        for (; j < cnt; j++) addRow(__shfl_sync(0xffffffffu, idx, j));
    }
    float inv = g_invdeg[warp];
    float f[4] = {acc.x * inv, acc.y * inv, acc.z * inv, acc.w * inv};
    long long o = (long long)warp * DIM + lane * 4;
    __nv_bfloat162 h01, h23, l01, l23;
    __nv_bfloat16 h0 = __float2bfloat16(f[0]);
    __nv_bfloat16 h1 = __float2bfloat16(f[1]);
    __nv_bfloat16 h2 = __float2bfloat16(f[2]);
    __nv_bfloat16 h3 = __float2bfloat16(f[3]);
    h01.x = h0; h01.y = h1; h23.x = h2; h23.y = h3;
    l01.x = __float2bfloat16(f[0] - __bfloat162float(h0));
    l01.y = __float2bfloat16(f[1] - __bfloat162float(h1));
    l23.x = __float2bfloat16(f[2] - __bfloat162float(h2));
    l23.y = __float2bfloat16(f[3] - __bfloat162float(h3));
    *(__nv_bfloat162*)(g_gh + o)     = h01;
    *(__nv_bfloat162*)(g_gh + o + 2) = h23;
    *(__nv_bfloat162*)(g_gl + o)     = l01;
    *(__nv_bfloat162*)(g_gl + o + 2) = l23;
}

// ---------------- persistent 16-warp mma.sync bf16-split GEMM ----------------
// D = Ah*Wh + Ah*Wl + Al*Wh over pre-split bf16 planes. 512 threads/CTA,
// warp grid 4x4 (warp tile m32 x NTILE/4), cp.async double-buffered A.

#define MMA_BF16(d, a, b)                                                     \
    asm volatile(                                                             \
        "mma.sync.aligned.m16n8k16.row.col.f32.bf16.bf16.f32 "                \
        "{%0,%1,%2,%3}, {%4,%5,%6,%7}, {%8,%9}, {%0,%1,%2,%3};"               \
        : "+f"((d)[0]), "+f"((d)[1]), "+f"((d)[2]), "+f"((d)[3])              \
        : "r"((a)[0]), "r"((a)[1]), "r"((a)[2]), "r"((a)[3]),                 \
          "r"((b)[0]), "r"((b)[1]))

#define LDSM_X4(r0, r1, r2, r3, addr)                                         \
    asm volatile("ldmatrix.sync.aligned.m8n8.x4.shared.b16 {%0,%1,%2,%3}, [%4];" \
        : "=r"(r0), "=r"(r1), "=r"(r2), "=r"(r3) : "r"(addr))

#define CP_ASYNC16(dst, src)                                                  \
    asm volatile("cp.async.cg.shared.global [%0], [%1], 16;"                  \
                 :: "r"(dst), "l"(src))
#define CP_COMMIT()  asm volatile("cp.async.commit_group;" ::: "memory")
#define CP_WAIT(n)   asm volatile("cp.async.wait_group %0;" :: "n"(n) : "memory")

__device__ __forceinline__ uint32_t smem_u32(const void* p) {
    uint32_t a;
    asm("{ .reg .u64 t; cvta.to.shared.u64 t, %1; cvt.u32.u64 %0, t; }"
        : "=r"(a) : "l"(p));
    return a;
}

template <int KTOT, int NTILE, bool RELU, bool DUAL, bool WPL, bool WF16, bool WF32>
__global__ void __launch_bounds__(512, 1)
mma_gemm(const __nv_bfloat16* __restrict__ A1H, const __nv_bfloat16* __restrict__ A1L,
         const __nv_bfloat16* __restrict__ A2H, const __nv_bfloat16* __restrict__ A2L,
         const float* __restrict__ W1, const float* __restrict__ W2,
         const float* __restrict__ bias,
         __nv_bfloat16* __restrict__ outH, __nv_bfloat16* __restrict__ outL,
         __half* __restrict__ out16, float* __restrict__ outF, int M) {
    constexpr int NFRAG = NTILE / 32;        // n8 frags per warp (4 or 2)
    constexpr int MF    = 2;                 // m16 frags per warp (m32)
    constexpr int KC     = 64;
    constexpr int NCHUNK = KTOT / KC;
    constexpr int SA = KC + 8;
    constexpr int SB = KTOT + 8;
    constexpr int ABYTES = 128 * SA * 2;     // one stage, one plane

    extern __shared__ __align__(16) __nv_bfloat16 smem[];
    __nv_bfloat16* WH = smem;                        // [NTILE][SB]
    __nv_bfloat16* WL = WH + NTILE * SB;

    const uint32_t sbase = smem_u32(smem);
    const int tid  = threadIdx.x;
    const int wid  = tid >> 5;
    const int lane = tid & 31;
    const int g    = lane >> 2;
    const int tq   = lane & 3;
    const int l8   = lane & 7;
    const int sel  = lane >> 3;

    // --- stage W transposed [n][k], split hi/lo (once per CTA) ---
    for (int idx = tid; idx < KTOT * NTILE; idx += 512) {
        int k = idx / NTILE, n = idx % NTILE;
        float w = (DUAL && k >= 128) ? W2[(k - 128) * NTILE + n]
                                     : W1[k * NTILE + n];
        __nv_bfloat16 h = __float2bfloat16(w);
        WH[n * SB + k] = h;
        WL[n * SB + k] = __float2bfloat16(w - __bfloat162float(h));
    }

    const uint32_t whB = sbase;
    const uint32_t wlB = sbase + (uint32_t)(NTILE * SB) * 2;
    const uint32_t ahB = wlB + (uint32_t)(NTILE * SB) * 2;   // [2 stages][128][SA]
    const uint32_t alB = ahB + 2 * ABYTES;

    // --- async A staging: 2048 x 16B per chunk (hi+lo planes), 4/thread ---
    auto stageA = [&](int row0, int c, int s) {
        const __nv_bfloat16 *ph, *pl; int kb;
        if (DUAL && c >= NCHUNK / 2) { ph = A2H; pl = A2L; kb = (c - NCHUNK / 2) * KC; }
        else                         { ph = A1H; pl = A1L; kb = c * KC; }
        const uint32_t ahD = ahB + (uint32_t)s * ABYTES;
        const uint32_t alD = alB + (uint32_t)s * ABYTES;
#pragma unroll
        for (int it = 0; it < 4; it++) {
            int idx = tid + it * 512;            // 0..2047
            int plane = idx >> 10;
            int rem = idx & 1023;
            int r = rem >> 3, q = rem & 7;
            long long gr = row0 + r;
            if (gr > M - 1) gr = M - 1;          // clamp (rows >= M never stored)
            const __nv_bfloat16* src = (plane ? pl : ph) + gr * DIM + kb + q * 8;
            uint32_t dst = (plane ? alD : ahD) + (uint32_t)(r * SA + q * 8) * 2;
            CP_ASYNC16(dst, src);
        }
        CP_COMMIT();
    };

    // 4x4 warp grid: warp tile m32 x (NTILE/4)
    const int cw = wid & 3;                  // col group 0..3
    const int rw = wid >> 2;                 // row group 0..3
    const int n0 = cw * (NTILE / 4);
    const int wr0 = rw * 32;

    const int a_row_l = l8 + ((sel & 1) << 3);
    const int a_kadd  = (sel >> 1) << 3;
    const int b_row_l = l8 + ((sel >> 1) << 3);
    const int b_kadd  = (sel & 1) << 3;

    const int NT = (M + 127) >> 7;
    __syncthreads();   // W visible before first MMA

    for (int tile = blockIdx.x; tile < NT; tile += gridDim.x) {
        const int row0 = tile << 7;

        float acc[MF][NFRAG][4];
#pragma unroll
        for (int mf = 0; mf < MF; mf++)
#pragma unroll
            for (int nf = 0; nf < NFRAG; nf++)
#pragma unroll
                for (int j = 0; j < 4; j++) acc[mf][nf][j] = 0.f;

        stageA(row0, 0, 0);

#pragma unroll 1
        for (int c = 0; c < NCHUNK; c++) {
            if (c + 1 < NCHUNK) { stageA(row0, c + 1, (c + 1) & 1); CP_WAIT(1); }
            else                { CP_WAIT(0); }
            __syncthreads();

            const uint32_t ast = (uint32_t)((c & 1)) * ABYTES;
#pragma unroll
            for (int ks = 0; ks < KC / 16; ks++) {
                const int k0 = ks * 16;
                const int kg = c * KC + k0;

                uint32_t afh[MF][4], afl[MF][4];
#pragma unroll
                for (int mf = 0; mf < MF; mf++) {
                    uint32_t ao = (uint32_t)((wr0 + mf * 16 + a_row_l) * SA
                                             + k0 + a_kadd) * 2;
                    LDSM_X4(afh[mf][0], afh[mf][1], afh[mf][2], afh[mf][3],
                            ahB + ast + ao);
                    LDSM_X4(afl[mf][0], afl[mf][1], afl[mf][2], afl[mf][3],
                            alB + ast + ao);
                }
                uint32_t bh[NFRAG][2], bl[NFRAG][2];
#pragma unroll
                for (int nfp = 0; nfp < NFRAG / 2; nfp++) {
                    uint32_t bo = (uint32_t)((n0 + nfp * 16 + b_row_l) * SB
                                             + kg + b_kadd) * 2;
                    LDSM_X4(bh[2 * nfp][0], bh[2 * nfp][1],
                            bh[2 * nfp + 1][0], bh[2 * nfp + 1][1], whB + bo);
                    LDSM_X4(bl[2 * nfp][0], bl[2 * nfp][1],
                            bl[2 * nfp + 1][0], bl[2 * nfp + 1][1], wlB + bo);
                }
#pragma unroll
                for (int nf = 0; nf < NFRAG; nf++)
#pragma unroll
                    for (int mf = 0; mf < MF; mf++) {
                        MMA_BF16(acc[mf][nf], afh[mf], bh[nf]);
                        MMA_BF16(acc[mf][nf], afh[mf], bl[nf]);
                        MMA_BF16(acc[mf][nf], afl[mf], bh[nf]);
                    }
            }
            __syncthreads();   // all reads done before next stage overwrites
        }

        // --- epilogue: bias (+relu), plane/fp16/fp32 stores ---
#pragma unroll
        for (int mf = 0; mf < MF; mf++) {
#pragma unroll
            for (int nf = 0; nf < NFRAG; nf++) {
                int col = n0 + nf * 8 + 2 * tq;
                int r = row0 + wr0 + mf * 16 + g;
                float b0 = __ldg(&bias[col]);
                float b1 = __ldg(&bias[col + 1]);
                float v[2][2] = {{acc[mf][nf][0] + b0, acc[mf][nf][1] + b1},
                                 {acc[mf][nf][2] + b0, acc[mf][nf][3] + b1}};
#pragma unroll
                for (int hrow = 0; hrow < 2; hrow++) {
                    int rr = r + hrow * 8;
                    if (rr >= M) continue;
                    float v0 = v[hrow][0], v1 = v[hrow][1];
                    if (RELU) { v0 = fmaxf(v0, 0.f); v1 = fmaxf(v1, 0.f); }
                    long long o = (long long)rr * NTILE + col;
                    if (WPL) {
                        __nv_bfloat162 hh, ll;
                        hh.x = __float2bfloat16(v0);
                        hh.y = __float2bfloat16(v1);
                        ll.x = __float2bfloat16(v0 - __bfloat162float(hh.x));
                        ll.y = __float2bfloat16(v1 - __bfloat162float(hh.y));
                        *(__nv_bfloat162*)(outH + o) = hh;
                        *(__nv_bfloat162*)(outL + o) = ll;
                    }
                    if (WF16)
                        *(__half2*)(out16 + o) = __floats2half2_rn(v0, v1);
                    if (WF32)
                        *(float2*)(outF + o) = make_float2(v0, v1);
                }
            }
        }
    }
}

// ---------------- launch ------------------------------------------------------
extern "C" void kernel_launch(void* const* d_in, const int* in_sizes, int n_in,
                              void* d_out, int out_size) {
    (void)in_sizes; (void)n_in; (void)out_size;
    const float* features = (const float*)d_in[0];
    const int*   src      = (const int*)  d_in[1];
    const int*   dst      = (const int*)  d_in[2];
    const float* W_self1  = (const float*)d_in[3];
    const float* W_neigh1 = (const float*)d_in[4];
    const float* b1       = (const float*)d_in[5];
    const float* W_self2  = (const float*)d_in[6];
    const float* W_neigh2 = (const float*)d_in[7];
    const float* b2       = (const float*)d_in[8];
    const float* W_out    = (const float*)d_in[9];
    const float* b_out    = (const float*)d_in[10];
    float*       out      = (float*)d_out;

    __nv_bfloat16 *fh, *fl, *gh, *gl, *h1h, *h1l, *h2h, *h2l;
    __half* p16; int* degp;
    cudaGetSymbolAddress((void**)&fh,  g_fh);
    cudaGetSymbolAddress((void**)&fl,  g_fl);
    cudaGetSymbolAddress((void**)&gh,  g_gh);
    cudaGetSymbolAddress((void**)&gl,  g_gl);
    cudaGetSymbolAddress((void**)&h1h, g_h1h);
    cudaGetSymbolAddress((void**)&h1l, g_h1l);
    cudaGetSymbolAddress((void**)&h2h, g_h2h);
    cudaGetSymbolAddress((void**)&h2l, g_h2l);
    cudaGetSymbolAddress((void**)&p16, g_p16);
    cudaGetSymbolAddress((void**)&degp, g_deg);

    const int SMEM_L = (2 * 128 * (256 + 8) + 4 * 128 * 72) * 2;  // 208896
    const int SMEM_O = (2 * 64  * (128 + 8) + 4 * 128 * 72) * 2;  // 108544
    cudaFuncSetAttribute(mma_gemm<256, 128, true, true, true, true, false>,
                         cudaFuncAttributeMaxDynamicSharedMemorySize, SMEM_L);
    cudaFuncSetAttribute(mma_gemm<256, 128, true, true, true, false, false>,
                         cudaFuncAttributeMaxDynamicSharedMemorySize, SMEM_L);
    cudaFuncSetAttribute(mma_gemm<128, 64, false, false, false, false, true>,
                         cudaFuncAttributeMaxDynamicSharedMemorySize, SMEM_O);

    const int EB = (N_EDGES + 255) / 256;          // 6250
    const int NB = (N_NODES + 255) / 256;          // 391
    const int GB = (N_NODES * 32 + 255) / 256;     // 12500 (warp per node)
    const int CB = (N_NODES * DIM / 4 + 255) / 256;
    const int PG = 148;

    // 0) zero degrees
    cudaMemsetAsync(degp, 0, N_NODES * sizeof(int));

    // 1-5) CSR build + feature planes
    count_deg_kernel<<<EB, 256>>>(dst);
    prep_kernel<<<CB, 256>>>(features, N_NODES * DIM / 4);
    degsum_kernel<<<NB, 256>>>();
    writeoff_fused_kernel<<<NB, 256>>>();
    build_csr_kernel<<<EB, 256>>>(src, dst);

    // 6-7) layer 1: gather + dual GEMM (writes h1 planes + fp16 plane)
    gather_mean_f16_kernel<<<GB, 256>>>(p16);
    mma_gemm<256, 128, true, true, true, true, false><<<PG, 512, SMEM_L>>>(
        fh, fl, gh, gl, W_self1, W_neigh1, b1, h1h, h1l, p16, nullptr, N_NODES);

    // 8-9) layer 2: gather + dual GEMM (writes h2 planes)
    gather_mean_f16_kernel<<<GB, 256>>>(p16);
    mma_gemm<256, 128, true, true, true, false, false><<<PG, 512, SMEM_L>>>(
        h1h, h1l, gh, gl, W_self2, W_neigh2, b2, h2h, h2l, nullptr, nullptr, N_NODES);

    // 10) output projection -> fp32 d_out
    mma_gemm<128, 64, false, false, false, false, true><<<PG, 512, SMEM_O>>>(
        h2h, h2l, nullptr, nullptr, W_out, nullptr, b_out,
        nullptr, nullptr, nullptr, out, N_NODES);
}

// round 13
// speedup vs baseline: 2.4442x; 1.0385x over previous
#include <cuda_runtime.h>
#include <cuda_bf16.h>
#include <cuda_fp16.h>
#include <cstdint>

#define N_NODES 100000
#define N_EDGES 1600000
#define DIM     128

// ---------------- scratch (device globals; no allocation in kernel_launch) ---
__device__ int   g_deg[N_NODES];
__device__ int   g_off[N_NODES + 1];
__device__ int   g_cur[N_NODES];
__device__ int   g_csr[N_EDGES];
__device__ float g_invdeg[N_NODES];
// bf16 hi/lo plane pairs (pre-split GEMM A operands)
__device__ __nv_bfloat16 g_fh [(long long)N_NODES * DIM];
__device__ __nv_bfloat16 g_fl [(long long)N_NODES * DIM];
__device__ __nv_bfloat16 g_gh [(long long)N_NODES * DIM];
__device__ __nv_bfloat16 g_gl [(long long)N_NODES * DIM];
__device__ __nv_bfloat16 g_h1h[(long long)N_NODES * DIM];
__device__ __nv_bfloat16 g_h1l[(long long)N_NODES * DIM];
__device__ __nv_bfloat16 g_h2h[(long long)N_NODES * DIM];
__device__ __nv_bfloat16 g_h2l[(long long)N_NODES * DIM];
__device__ __half g_p16[(long long)N_NODES * DIM];   // fp16 gather plane

// ---------------- prep: features -> bf16 hi/lo planes + fp16 plane + zero deg
__global__ void prep_kernel(const float* __restrict__ in, int n4) {
    int i = blockIdx.x * blockDim.x + threadIdx.x;
    if (i < N_NODES) g_deg[i] = 0;            // runs before count_deg (stream order)
    if (i >= n4) return;
    float4 v = *(const float4*)(in + (long long)i * 4);
    float f[4] = {v.x, v.y, v.z, v.w};
    __nv_bfloat162 h01, h23, l01, l23;
    __nv_bfloat16 h0 = __float2bfloat16(f[0]);
    __nv_bfloat16 h1 = __float2bfloat16(f[1]);
    __nv_bfloat16 h2 = __float2bfloat16(f[2]);
    __nv_bfloat16 h3 = __float2bfloat16(f[3]);
    h01.x = h0; h01.y = h1; h23.x = h2; h23.y = h3;
    l01.x = __float2bfloat16(f[0] - __bfloat162float(h0));
    l01.y = __float2bfloat16(f[1] - __bfloat162float(h1));
    l23.x = __float2bfloat16(f[2] - __bfloat162float(h2));
    l23.y = __float2bfloat16(f[3] - __bfloat162float(h3));
    *(__nv_bfloat162*)(g_fh + (long long)i * 4)     = h01;
    *(__nv_bfloat162*)(g_fh + (long long)i * 4 + 2) = h23;
    *(__nv_bfloat162*)(g_fl + (long long)i * 4)     = l01;
    *(__nv_bfloat162*)(g_fl + (long long)i * 4 + 2) = l23;
    *(__half2*)(g_p16 + (long long)i * 4)     = __floats2half2_rn(f[0], f[1]);
    *(__half2*)(g_p16 + (long long)i * 4 + 2) = __floats2half2_rn(f[2], f[3]);
}

// ---------------- CSR build --------------------------------------------------
__global__ void count_deg_kernel(const int* __restrict__ dst) {
    int i = blockIdx.x * blockDim.x + threadIdx.x;
    if (i < N_EDGES) atomicAdd(&g_deg[dst[i]], 1);
}
// fused scan: block b direct-sums deg[0..b*256) for its base, then local scan
__global__ void scanoff_kernel() {
    __shared__ int red[256];
    __shared__ int sh[256];
    int b = blockIdx.x, t = threadIdx.x;
    int i = b * 256 + t;
    int lim = b * 256;
    int p = 0;
    for (int j = t; j < lim; j += 256) p += g_deg[j];
    red[t] = p;
    int dg = (i < N_NODES) ? g_deg[i] : 0;
    sh[t] = dg;
    __syncthreads();
    for (int d = 128; d > 0; d >>= 1) {
        if (t < d) red[t] += red[t + d];
        __syncthreads();
    }
    int base = red[0];
    for (int d = 1; d < 256; d <<= 1) {
        int v = (t >= d) ? sh[t - d] : 0;
        __syncthreads();
        sh[t] += v;
        __syncthreads();
    }
    if (i < N_NODES) {
        int off = base + sh[t] - dg;
        g_off[i] = off;
        g_cur[i] = off;
        g_invdeg[i] = 1.0f / (float)(dg > 0 ? dg : 1);
        if (i == N_NODES - 1) g_off[N_NODES] = off + dg;
    }
}
__global__ void build_csr_kernel(const int* __restrict__ src,
                                 const int* __restrict__ dst) {
    int i = blockIdx.x * blockDim.x + threadIdx.x;
    if (i < N_EDGES) {
        int d = dst[i];
        int p = atomicAdd(&g_cur[d], 1);
        g_csr[p] = src[i];
    }
}

// ---------------- gather-side mean aggregation (warp per node, fp16 src) -----
__global__ void gather_mean_f16_kernel(const __half* __restrict__ hsrc) {
    int warp = (blockIdx.x * blockDim.x + threadIdx.x) >> 5;
    if (warp >= N_NODES) return;
    int lane = threadIdx.x & 31;
    int s0 = g_off[warp];
    int s1 = g_off[warp + 1];
    float4 acc = make_float4(0.f, 0.f, 0.f, 0.f);

    auto addRow = [&](int node) {
        uint2 raw = *(const uint2*)(hsrc + (long long)node * DIM + lane * 4);
        float2 f0 = __half22float2(*(__half2*)&raw.x);
        float2 f1 = __half22float2(*(__half2*)&raw.y);
        acc.x += f0.x; acc.y += f0.y; acc.z += f1.x; acc.w += f1.y;
    };

    for (int e = s0; e < s1; e += 32) {
        int idx = (e + lane < s1) ? g_csr[e + lane] : 0;
        int cnt = s1 - e; if (cnt > 32) cnt = 32;
        int j = 0;
        for (; j + 8 <= cnt; j += 8) {
            int n0 = __shfl_sync(0xffffffffu, idx, j + 0);
            int n1 = __shfl_sync(0xffffffffu, idx, j + 1);
            int n2 = __shfl_sync(0xffffffffu, idx, j + 2);
            int n3 = __shfl_sync(0xffffffffu, idx, j + 3);
            int n4 = __shfl_sync(0xffffffffu, idx, j + 4);
            int n5 = __shfl_sync(0xffffffffu, idx, j + 5);
            int n6 = __shfl_sync(0xffffffffu, idx, j + 6);
            int n7 = __shfl_sync(0xffffffffu, idx, j + 7);
            uint2 r0 = *(const uint2*)(hsrc + (long long)n0 * DIM + lane * 4);
            uint2 r1 = *(const uint2*)(hsrc + (long long)n1 * DIM + lane * 4);
            uint2 r2 = *(const uint2*)(hsrc + (long long)n2 * DIM + lane * 4);
            uint2 r3 = *(const uint2*)(hsrc + (long long)n3 * DIM + lane * 4);
            uint2 r4 = *(const uint2*)(hsrc + (long long)n4 * DIM + lane * 4);
            uint2 r5 = *(const uint2*)(hsrc + (long long)n5 * DIM + lane * 4);
            uint2 r6 = *(const uint2*)(hsrc + (long long)n6 * DIM + lane * 4);
            uint2 r7 = *(const uint2*)(hsrc + (long long)n7 * DIM + lane * 4);
            uint2 rs[8] = {r0, r1, r2, r3, r4, r5, r6, r7};
#pragma unroll
            for (int q = 0; q < 8; q++) {
                float2 f0 = __half22float2(*(__half2*)&rs[q].x);
                float2 f1 = __half22float2(*(__half2*)&rs[q].y);
                acc.x += f0.x; acc.y += f0.y; acc.z += f1.x; acc.w += f1.y;
            }
        }
        for (; j < cnt; j++) addRow(__shfl_sync(0xffffffffu, idx, j));
    }
    float inv = g_invdeg[warp];
    float f[4] = {acc.x * inv, acc.y * inv, acc.z * inv, acc.w * inv};
    long long o = (long long)warp * DIM + lane * 4;
    __nv_bfloat162 h01, h23, l01, l23;
    __nv_bfloat16 h0 = __float2bfloat16(f[0]);
    __nv_bfloat16 h1 = __float2bfloat16(f[1]);
    __nv_bfloat16 h2 = __float2bfloat16(f[2]);
    __nv_bfloat16 h3 = __float2bfloat16(f[3]);
    h01.x = h0; h01.y = h1; h23.x = h2; h23.y = h3;
    l01.x = __float2bfloat16(f[0] - __bfloat162float(h0));
    l01.y = __float2bfloat16(f[1] - __bfloat162float(h1));
    l23.x = __float2bfloat16(f[2] - __bfloat162float(h2));
    l23.y = __float2bfloat16(f[3] - __bfloat162float(h3));
    *(__nv_bfloat162*)(g_gh + o)     = h01;
    *(__nv_bfloat162*)(g_gh + o + 2) = h23;
    *(__nv_bfloat162*)(g_gl + o)     = l01;
    *(__nv_bfloat162*)(g_gl + o + 2) = l23;
}

// ---------------- persistent 16-warp mma.sync bf16-split GEMM ----------------
// D = Ah*Wh + Ah*Wl + Al*Wh over pre-split bf16 planes. 512 threads/CTA,
// warp grid 4x4, cp.async double-buffered A with CROSS-TILE prefetch.

#define MMA_BF16(d, a, b)                                                     \
    asm volatile(                                                             \
        "mma.sync.aligned.m16n8k16.row.col.f32.bf16.bf16.f32 "                \
        "{%0,%1,%2,%3}, {%4,%5,%6,%7}, {%8,%9}, {%0,%1,%2,%3};"               \
        : "+f"((d)[0]), "+f"((d)[1]), "+f"((d)[2]), "+f"((d)[3])              \
        : "r"((a)[0]), "r"((a)[1]), "r"((a)[2]), "r"((a)[3]),                 \
          "r"((b)[0]), "r"((b)[1]))

#define LDSM_X4(r0, r1, r2, r3, addr)                                         \
    asm volatile("ldmatrix.sync.aligned.m8n8.x4.shared.b16 {%0,%1,%2,%3}, [%4];" \
        : "=r"(r0), "=r"(r1), "=r"(r2), "=r"(r3) : "r"(addr))

#define CP_ASYNC16(dst, src)                                                  \
    asm volatile("cp.async.cg.shared.global [%0], [%1], 16;"                  \
                 :: "r"(dst), "l"(src))
#define CP_COMMIT()  asm volatile("cp.async.commit_group;" ::: "memory")
#define CP_WAIT(n)   asm volatile("cp.async.wait_group %0;" :: "n"(n) : "memory")

__device__ __forceinline__ uint32_t smem_u32(const void* p) {
    uint32_t a;
    asm("{ .reg .u64 t; cvta.to.shared.u64 t, %1; cvt.u32.u64 %0, t; }"
        : "=r"(a) : "l"(p));
    return a;
}

template <int KTOT, int NTILE, bool RELU, bool DUAL, bool WPL, bool WF16, bool WF32>
__global__ void __launch_bounds__(512, 1)
mma_gemm(const __nv_bfloat16* __restrict__ A1H, const __nv_bfloat16* __restrict__ A1L,
         const __nv_bfloat16* __restrict__ A2H, const __nv_bfloat16* __restrict__ A2L,
         const float* __restrict__ W1, const float* __restrict__ W2,
         const float* __restrict__ bias,
         __nv_bfloat16* __restrict__ outH, __nv_bfloat16* __restrict__ outL,
         __half* __restrict__ out16, float* __restrict__ outF, int M) {
    constexpr int NFRAG = NTILE / 32;        // n8 frags per warp (4 or 2)
    constexpr int MF    = 2;                 // m16 frags per warp (m32)
    constexpr int KC     = 64;
    constexpr int NCHUNK = KTOT / KC;        // even (4 or 2)
    constexpr int SA = KC + 8;
    constexpr int SB = KTOT + 8;
    constexpr int ABYTES = 128 * SA * 2;     // one stage, one plane

    extern __shared__ __align__(16) __nv_bfloat16 smem[];
    __nv_bfloat16* WH = smem;                        // [NTILE][SB]
    __nv_bfloat16* WL = WH + NTILE * SB;

    const uint32_t sbase = smem_u32(smem);
    const int tid  = threadIdx.x;
    const int wid  = tid >> 5;
    const int lane = tid & 31;
    const int g    = lane >> 2;
    const int tq   = lane & 3;
    const int l8   = lane & 7;
    const int sel  = lane >> 3;

    // --- stage W transposed [n][k], split hi/lo (once per CTA) ---
    for (int idx = tid; idx < KTOT * NTILE; idx += 512) {
        int k = idx / NTILE, n = idx % NTILE;
        float w = (DUAL && k >= 128) ? W2[(k - 128) * NTILE + n]
                                     : W1[k * NTILE + n];
        __nv_bfloat16 h = __float2bfloat16(w);
        WH[n * SB + k] = h;
        WL[n * SB + k] = __float2bfloat16(w - __bfloat162float(h));
    }

    const uint32_t whB = sbase;
    const uint32_t wlB = sbase + (uint32_t)(NTILE * SB) * 2;
    const uint32_t ahB = wlB + (uint32_t)(NTILE * SB) * 2;   // [2 stages][128][SA]
    const uint32_t alB = ahB + 2 * ABYTES;

    // --- async A staging: 2048 x 16B per chunk (hi+lo planes), 4/thread ---
    auto stageA = [&](int row0, int c, int s) {
        const __nv_bfloat16 *ph, *pl; int kb;
        if (DUAL && c >= NCHUNK / 2) { ph = A2H; pl = A2L; kb = (c - NCHUNK / 2) * KC; }
        else                         { ph = A1H; pl = A1L; kb = c * KC; }
        const uint32_t ahD = ahB + (uint32_t)s * ABYTES;
        const uint32_t alD = alB + (uint32_t)s * ABYTES;
#pragma unroll
        for (int it = 0; it < 4; it++) {
            int idx = tid + it * 512;            // 0..2047
            int plane = idx >> 10;
            int rem = idx & 1023;
            int r = rem >> 3, q = rem & 7;
            long long gr = row0 + r;
            if (gr > M - 1) gr = M - 1;          // clamp (rows >= M never stored)
            const __nv_bfloat16* src = (plane ? pl : ph) + gr * DIM + kb + q * 8;
            uint32_t dst = (plane ? alD : ahD) + (uint32_t)(r * SA + q * 8) * 2;
            CP_ASYNC16(dst, src);
        }
        CP_COMMIT();
    };

    // 4x4 warp grid: warp tile m32 x (NTILE/4)
    const int cw = wid & 3;                  // col group 0..3
    const int rw = wid >> 2;                 // row group 0..3
    const int n0 = cw * (NTILE / 4);
    const int wr0 = rw * 32;

    const int a_row_l = l8 + ((sel & 1) << 3);
    const int a_kadd  = (sel >> 1) << 3;
    const int b_row_l = l8 + ((sel >> 1) << 3);
    const int b_kadd  = (sel & 1) << 3;

    const int NT = (M + 127) >> 7;
    bool pf = false;                         // next tile's chunk0 prefetched?
    __syncthreads();   // W visible before first MMA

    for (int tile = blockIdx.x; tile < NT; tile += gridDim.x) {
        const int row0 = tile << 7;

        float acc[MF][NFRAG][4];
#pragma unroll
        for (int mf = 0; mf < MF; mf++)
#pragma unroll
            for (int nf = 0; nf < NFRAG; nf++)
#pragma unroll
                for (int j = 0; j < 4; j++) acc[mf][nf][j] = 0.f;

        if (!pf) stageA(row0, 0, 0);
        pf = false;

#pragma unroll 1
        for (int c = 0; c < NCHUNK; c++) {
            bool issued = true;
            if (c + 1 < NCHUNK) {
                stageA(row0, c + 1, (c + 1) & 1);
            } else {
                int ntile = tile + gridDim.x;
                if (ntile < NT) { stageA(ntile << 7, 0, 0); pf = true; }
                else issued = false;
            }
            if (issued) { CP_WAIT(1); } else { CP_WAIT(0); }
            __syncthreads();

            const uint32_t ast = (uint32_t)((c & 1)) * ABYTES;
#pragma unroll
            for (int ks = 0; ks < KC / 16; ks++) {
                const int k0 = ks * 16;
                const int kg = c * KC + k0;

                uint32_t afh[MF][4], afl[MF][4];
#pragma unroll
                for (int mf = 0; mf < MF; mf++) {
                    uint32_t ao = (uint32_t)((wr0 + mf * 16 + a_row_l) * SA
                                             + k0 + a_kadd) * 2;
                    LDSM_X4(afh[mf][0], afh[mf][1], afh[mf][2], afh[mf][3],
                            ahB + ast + ao);
                    LDSM_X4(afl[mf][0], afl[mf][1], afl[mf][2], afl[mf][3],
                            alB + ast + ao);
                }
                uint32_t bh[NFRAG][2], bl[NFRAG][2];
#pragma unroll
                for (int nfp = 0; nfp < NFRAG / 2; nfp++) {
                    uint32_t bo = (uint32_t)((n0 + nfp * 16 + b_row_l) * SB
                                             + kg + b_kadd) * 2;
                    LDSM_X4(bh[2 * nfp][0], bh[2 * nfp][1],
                            bh[2 * nfp + 1][0], bh[2 * nfp + 1][1], whB + bo);
                    LDSM_X4(bl[2 * nfp][0], bl[2 * nfp][1],
                            bl[2 * nfp + 1][0], bl[2 * nfp + 1][1], wlB + bo);
                }
#pragma unroll
                for (int nf = 0; nf < NFRAG; nf++)
#pragma unroll
                    for (int mf = 0; mf < MF; mf++) {
                        MMA_BF16(acc[mf][nf], afh[mf], bh[nf]);
                        MMA_BF16(acc[mf][nf], afh[mf], bl[nf]);
                        MMA_BF16(acc[mf][nf], afl[mf], bh[nf]);
                    }
            }
            __syncthreads();   // all reads done before next stage overwrites
        }

        // --- epilogue: bias (+relu), plane/fp16/fp32 stores ---
#pragma unroll
        for (int mf = 0; mf < MF; mf++) {
#pragma unroll
            for (int nf = 0; nf < NFRAG; nf++) {
                int col = n0 + nf * 8 + 2 * tq;
                int r = row0 + wr0 + mf * 16 + g;
                float b0 = __ldg(&bias[col]);
                float b1 = __ldg(&bias[col + 1]);
                float v[2][2] = {{acc[mf][nf][0] + b0, acc[mf][nf][1] + b1},
                                 {acc[mf][nf][2] + b0, acc[mf][nf][3] + b1}};
#pragma unroll
                for (int hrow = 0; hrow < 2; hrow++) {
                    int rr = r + hrow * 8;
                    if (rr >= M) continue;
                    float v0 = v[hrow][0], v1 = v[hrow][1];
                    if (RELU) { v0 = fmaxf(v0, 0.f); v1 = fmaxf(v1, 0.f); }
                    long long o = (long long)rr * NTILE + col;
                    if (WPL) {
                        __nv_bfloat162 hh, ll;
                        hh.x = __float2bfloat16(v0);
                        hh.y = __float2bfloat16(v1);
                        ll.x = __float2bfloat16(v0 - __bfloat162float(hh.x));
                        ll.y = __float2bfloat16(v1 - __bfloat162float(hh.y));
                        *(__nv_bfloat162*)(outH + o) = hh;
                        *(__nv_bfloat162*)(outL + o) = ll;
                    }
                    if (WF16)
                        *(__half2*)(out16 + o) = __floats2half2_rn(v0, v1);
                    if (WF32)
                        *(float2*)(outF + o) = make_float2(v0, v1);
                }
            }
        }
    }
}

// ---------------- launch ------------------------------------------------------
extern "C" void kernel_launch(void* const* d_in, const int* in_sizes, int n_in,
                              void* d_out, int out_size) {
    (void)in_sizes; (void)n_in; (void)out_size;
    const float* features = (const float*)d_in[0];
    const int*   src      = (const int*)  d_in[1];
    const int*   dst      = (const int*)  d_in[2];
    const float* W_self1  = (const float*)d_in[3];
    const float* W_neigh1 = (const float*)d_in[4];
    const float* b1       = (const float*)d_in[5];
    const float* W_self2  = (const float*)d_in[6];
    const float* W_neigh2 = (const float*)d_in[7];
    const float* b2       = (const float*)d_in[8];
    const float* W_out    = (const float*)d_in[9];
    const float* b_out    = (const float*)d_in[10];
    float*       out      = (float*)d_out;

    __nv_bfloat16 *fh, *fl, *gh, *gl, *h1h, *h1l, *h2h, *h2l;
    __half* p16;
    cudaGetSymbolAddress((void**)&fh,  g_fh);
    cudaGetSymbolAddress((void**)&fl,  g_fl);
    cudaGetSymbolAddress((void**)&gh,  g_gh);
    cudaGetSymbolAddress((void**)&gl,  g_gl);
    cudaGetSymbolAddress((void**)&h1h, g_h1h);
    cudaGetSymbolAddress((void**)&h1l, g_h1l);
    cudaGetSymbolAddress((void**)&h2h, g_h2h);
    cudaGetSymbolAddress((void**)&h2l, g_h2l);
    cudaGetSymbolAddress((void**)&p16, g_p16);

    const int SMEM_L = (2 * 128 * (256 + 8) + 4 * 128 * 72) * 2;  // 208896
    const int SMEM_O = (2 * 64  * (128 + 8) + 4 * 128 * 72) * 2;  // 108544
    cudaFuncSetAttribute(mma_gemm<256, 128, true, true, true, true, false>,
                         cudaFuncAttributeMaxDynamicSharedMemorySize, SMEM_L);
    cudaFuncSetAttribute(mma_gemm<256, 128, true, true, true, false, false>,
                         cudaFuncAttributeMaxDynamicSharedMemorySize, SMEM_L);
    cudaFuncSetAttribute(mma_gemm<128, 64, false, false, false, false, true>,
                         cudaFuncAttributeMaxDynamicSharedMemorySize, SMEM_O);

    const int EB = (N_EDGES + 255) / 256;          // 6250
    const int NB = (N_NODES + 255) / 256;          // 391
    const int GB = (N_NODES * 32 + 255) / 256;     // 12500 (warp per node)
    const int CB = (N_NODES * DIM / 4 + 255) / 256;
    const int PG = 148;

    // 1-4) feature planes (+deg zeroing) + CSR build
    prep_kernel<<<CB, 256>>>(features, N_NODES * DIM / 4);
    count_deg_kernel<<<EB, 256>>>(dst);
    scanoff_kernel<<<NB, 256>>>();
    build_csr_kernel<<<EB, 256>>>(src, dst);

    // 5-6) layer 1: gather (profiled slot) + dual GEMM
    gather_mean_f16_kernel<<<GB, 256>>>(p16);
    mma_gemm<256, 128, true, true, true, true, false><<<PG, 512, SMEM_L>>>(
        fh, fl, gh, gl, W_self1, W_neigh1, b1, h1h, h1l, p16, nullptr, N_NODES);

    // 7-8) layer 2: gather + dual GEMM (writes h2 planes)
    gather_mean_f16_kernel<<<GB, 256>>>(p16);
    mma_gemm<256, 128, true, true, true, false, false><<<PG, 512, SMEM_L>>>(
        h1h, h1l, gh, gl, W_self2, W_neigh2, b2, h2h, h2l, nullptr, nullptr, N_NODES);

    // 9) output projection -> fp32 d_out
    mma_gemm<128, 64, false, false, false, false, true><<<PG, 512, SMEM_O>>>(
        h2h, h2l, nullptr, nullptr, W_out, nullptr, b_out,
        nullptr, nullptr, nullptr, out, N_NODES);
}

// round 14
// speedup vs baseline: 3.1974x; 1.3082x over previous
#include <cuda_runtime.h>
#include <cuda_fp16.h>
#include <cstdint>

#define N_NODES 100000
#define N_EDGES 1600000
#define DIM     128

// ---------------- scratch (device globals; no allocation in kernel_launch) ---
__device__ int   g_deg[N_NODES];
__device__ int   g_off[N_NODES + 1];
__device__ int   g_cur[N_NODES];
__device__ int   g_csr[N_EDGES];
__device__ float g_invdeg[N_NODES];
// unified fp16 activation planes (GEMM A operands AND gather sources)
__device__ __half g_f16[(long long)N_NODES * DIM];   // features
__device__ __half g_g16[(long long)N_NODES * DIM];   // neighbor means (per layer)
__device__ __half g_h1 [(long long)N_NODES * DIM];   // layer-1 output
__device__ __half g_h2 [(long long)N_NODES * DIM];   // layer-2 output

// ---------------- prep: features -> fp16 plane + zero deg --------------------
__global__ void prep_kernel(const float* __restrict__ in, int n4) {
    int i = blockIdx.x * blockDim.x + threadIdx.x;
    if (i < N_NODES) g_deg[i] = 0;            // runs before count_deg (stream order)
    if (i >= n4) return;
    float4 v = *(const float4*)(in + (long long)i * 4);
    *(__half2*)(g_f16 + (long long)i * 4)     = __floats2half2_rn(v.x, v.y);
    *(__half2*)(g_f16 + (long long)i * 4 + 2) = __floats2half2_rn(v.z, v.w);
}

// ---------------- CSR build --------------------------------------------------
__global__ void count_deg_kernel(const int* __restrict__ dst) {
    int i = blockIdx.x * blockDim.x + threadIdx.x;
    if (i < N_EDGES) atomicAdd(&g_deg[dst[i]], 1);
}
// fused scan: block b direct-sums deg[0..b*256) for its base, then local scan
__global__ void scanoff_kernel() {
    __shared__ int red[256];
    __shared__ int sh[256];
    int b = blockIdx.x, t = threadIdx.x;
    int i = b * 256 + t;
    int lim = b * 256;
    int p = 0;
    for (int j = t; j < lim; j += 256) p += g_deg[j];
    red[t] = p;
    int dg = (i < N_NODES) ? g_deg[i] : 0;
    sh[t] = dg;
    __syncthreads();
    for (int d = 128; d > 0; d >>= 1) {
        if (t < d) red[t] += red[t + d];
        __syncthreads();
    }
    int base = red[0];
    for (int d = 1; d < 256; d <<= 1) {
        int v = (t >= d) ? sh[t - d] : 0;
        __syncthreads();
        sh[t] += v;
        __syncthreads();
    }
    if (i < N_NODES) {
        int off = base + sh[t] - dg;
        g_off[i] = off;
        g_cur[i] = off;
        g_invdeg[i] = 1.0f / (float)(dg > 0 ? dg : 1);
        if (i == N_NODES - 1) g_off[N_NODES] = off + dg;
    }
}
__global__ void build_csr_kernel(const int* __restrict__ src,
                                 const int* __restrict__ dst) {
    int i = blockIdx.x * blockDim.x + threadIdx.x;
    if (i < N_EDGES) {
        int d = dst[i];
        int p = atomicAdd(&g_cur[d], 1);
        g_csr[p] = src[i];
    }
}

// ---------------- gather-side mean aggregation (warp per node, fp16) ---------
__global__ void gather_mean_f16_kernel(const __half* __restrict__ hsrc) {
    int warp = (blockIdx.x * blockDim.x + threadIdx.x) >> 5;
    if (warp >= N_NODES) return;
    int lane = threadIdx.x & 31;
    int s0 = g_off[warp];
    int s1 = g_off[warp + 1];
    float4 acc = make_float4(0.f, 0.f, 0.f, 0.f);

    auto addRow = [&](int node) {
        uint2 raw = *(const uint2*)(hsrc + (long long)node * DIM + lane * 4);
        float2 f0 = __half22float2(*(__half2*)&raw.x);
        float2 f1 = __half22float2(*(__half2*)&raw.y);
        acc.x += f0.x; acc.y += f0.y; acc.z += f1.x; acc.w += f1.y;
    };

    for (int e = s0; e < s1; e += 32) {
        int idx = (e + lane < s1) ? g_csr[e + lane] : 0;
        int cnt = s1 - e; if (cnt > 32) cnt = 32;
        int j = 0;
        for (; j + 8 <= cnt; j += 8) {
            int n0 = __shfl_sync(0xffffffffu, idx, j + 0);
            int n1 = __shfl_sync(0xffffffffu, idx, j + 1);
            int n2 = __shfl_sync(0xffffffffu, idx, j + 2);
            int n3 = __shfl_sync(0xffffffffu, idx, j + 3);
            int n4 = __shfl_sync(0xffffffffu, idx, j + 4);
            int n5 = __shfl_sync(0xffffffffu, idx, j + 5);
            int n6 = __shfl_sync(0xffffffffu, idx, j + 6);
            int n7 = __shfl_sync(0xffffffffu, idx, j + 7);
            uint2 r0 = *(const uint2*)(hsrc + (long long)n0 * DIM + lane * 4);
            uint2 r1 = *(const uint2*)(hsrc + (long long)n1 * DIM + lane * 4);
            uint2 r2 = *(const uint2*)(hsrc + (long long)n2 * DIM + lane * 4);
            uint2 r3 = *(const uint2*)(hsrc + (long long)n3 * DIM + lane * 4);
            uint2 r4 = *(const uint2*)(hsrc + (long long)n4 * DIM + lane * 4);
            uint2 r5 = *(const uint2*)(hsrc + (long long)n5 * DIM + lane * 4);
            uint2 r6 = *(const uint2*)(hsrc + (long long)n6 * DIM + lane * 4);
            uint2 r7 = *(const uint2*)(hsrc + (long long)n7 * DIM + lane * 4);
            uint2 rs[8] = {r0, r1, r2, r3, r4, r5, r6, r7};
#pragma unroll
            for (int q = 0; q < 8; q++) {
                float2 f0 = __half22float2(*(__half2*)&rs[q].x);
                float2 f1 = __half22float2(*(__half2*)&rs[q].y);
                acc.x += f0.x; acc.y += f0.y; acc.z += f1.x; acc.w += f1.y;
            }
        }
        for (; j < cnt; j++) addRow(__shfl_sync(0xffffffffu, idx, j));
    }
    float inv = g_invdeg[warp];
    long long o = (long long)warp * DIM + lane * 4;
    *(__half2*)(g_g16 + o)     = __floats2half2_rn(acc.x * inv, acc.y * inv);
    *(__half2*)(g_g16 + o + 2) = __floats2half2_rn(acc.z * inv, acc.w * inv);
}

// ---------------- persistent 16-warp mma.sync fp16 2-term GEMM ---------------
// D = A*Wh + A*Wl : A single fp16 plane, W split into fp16 hi/lo (W err ~2^-23).
// 512 threads/CTA, warp grid 4x4, cp.async double-buffered A w/ cross-tile pf.

#define MMA_F16(d, a, b)                                                      \
    asm volatile(                                                             \
        "mma.sync.aligned.m16n8k16.row.col.f32.f16.f16.f32 "                  \
        "{%0,%1,%2,%3}, {%4,%5,%6,%7}, {%8,%9}, {%0,%1,%2,%3};"               \
        : "+f"((d)[0]), "+f"((d)[1]), "+f"((d)[2]), "+f"((d)[3])              \
        : "r"((a)[0]), "r"((a)[1]), "r"((a)[2]), "r"((a)[3]),                 \
          "r"((b)[0]), "r"((b)[1]))

#define LDSM_X4(r0, r1, r2, r3, addr)                                         \
    asm volatile("ldmatrix.sync.aligned.m8n8.x4.shared.b16 {%0,%1,%2,%3}, [%4];" \
        : "=r"(r0), "=r"(r1), "=r"(r2), "=r"(r3) : "r"(addr))

#define CP_ASYNC16(dst, src)                                                  \
    asm volatile("cp.async.cg.shared.global [%0], [%1], 16;"                  \
                 :: "r"(dst), "l"(src))
#define CP_COMMIT()  asm volatile("cp.async.commit_group;" ::: "memory")
#define CP_WAIT(n)   asm volatile("cp.async.wait_group %0;" :: "n"(n) : "memory")

__device__ __forceinline__ uint32_t smem_u32(const void* p) {
    uint32_t a;
    asm("{ .reg .u64 t; cvta.to.shared.u64 t, %1; cvt.u32.u64 %0, t; }"
        : "=r"(a) : "l"(p));
    return a;
}

template <int KTOT, int NTILE, bool RELU, bool DUAL, bool WF16, bool WF32>
__global__ void __launch_bounds__(512, 1)
mma_gemm(const __half* __restrict__ A1, const __half* __restrict__ A2,
         const float* __restrict__ W1, const float* __restrict__ W2,
         const float* __restrict__ bias,
         __half* __restrict__ out16, float* __restrict__ outF, int M) {
    constexpr int NFRAG = NTILE / 32;        // n8 frags per warp (4 or 2)
    constexpr int MF    = 2;                 // m16 frags per warp (m32)
    constexpr int KC     = 64;
    constexpr int NCHUNK = KTOT / KC;        // even (4 or 2)
    constexpr int SA = KC + 8;
    constexpr int SB = KTOT + 8;
    constexpr int ABYTES = 128 * SA * 2;     // one stage (single A plane)

    extern __shared__ __align__(16) __half smem[];
    __half* WH = smem;                       // [NTILE][SB]
    __half* WL = WH + NTILE * SB;

    const uint32_t sbase = smem_u32(smem);
    const int tid  = threadIdx.x;
    const int wid  = tid >> 5;
    const int lane = tid & 31;
    const int g    = lane >> 2;
    const int tq   = lane & 3;
    const int l8   = lane & 7;
    const int sel  = lane >> 3;

    // --- stage W transposed [n][k], split fp16 hi/lo (once per CTA) ---
    for (int idx = tid; idx < KTOT * NTILE; idx += 512) {
        int k = idx / NTILE, n = idx % NTILE;
        float w = (DUAL && k >= 128) ? W2[(k - 128) * NTILE + n]
                                     : W1[k * NTILE + n];
        __half h = __float2half_rn(w);
        WH[n * SB + k] = h;
        WL[n * SB + k] = __float2half_rn(w - __half2float(h));
    }

    const uint32_t whB = sbase;
    const uint32_t wlB = sbase + (uint32_t)(NTILE * SB) * 2;
    const uint32_t aB  = wlB + (uint32_t)(NTILE * SB) * 2;   // [2 stages][128][SA]

    // --- async A staging: 1024 x 16B per chunk (single plane), 2/thread ---
    auto stageA = [&](int row0, int c, int s) {
        const __half* pa; int kb;
        if (DUAL && c >= NCHUNK / 2) { pa = A2; kb = (c - NCHUNK / 2) * KC; }
        else                         { pa = A1; kb = c * KC; }
        const uint32_t aD = aB + (uint32_t)s * ABYTES;
#pragma unroll
        for (int it = 0; it < 2; it++) {
            int idx = tid + it * 512;            // 0..1023
            int r = idx >> 3, q = idx & 7;
            long long gr = row0 + r;
            if (gr > M - 1) gr = M - 1;          // clamp (rows >= M never stored)
            const __half* src = pa + gr * DIM + kb + q * 8;
            uint32_t dst = aD + (uint32_t)(r * SA + q * 8) * 2;
            CP_ASYNC16(dst, src);
        }
        CP_COMMIT();
    };

    // 4x4 warp grid: warp tile m32 x (NTILE/4)
    const int cw = wid & 3;
    const int rw = wid >> 2;
    const int n0 = cw * (NTILE / 4);
    const int wr0 = rw * 32;

    const int a_row_l = l8 + ((sel & 1) << 3);
    const int a_kadd  = (sel >> 1) << 3;
    const int b_row_l = l8 + ((sel >> 1) << 3);
    const int b_kadd  = (sel & 1) << 3;

    const int NT = (M + 127) >> 7;
    bool pf = false;                         // next tile's chunk0 prefetched?
    __syncthreads();   // W visible before first MMA

    for (int tile = blockIdx.x; tile < NT; tile += gridDim.x) {
        const int row0 = tile << 7;

        float acc[MF][NFRAG][4];
#pragma unroll
        for (int mf = 0; mf < MF; mf++)
#pragma unroll
            for (int nf = 0; nf < NFRAG; nf++)
#pragma unroll
                for (int j = 0; j < 4; j++) acc[mf][nf][j] = 0.f;

        if (!pf) stageA(row0, 0, 0);
        pf = false;

#pragma unroll 1
        for (int c = 0; c < NCHUNK; c++) {
            bool issued = true;
            if (c + 1 < NCHUNK) {
                stageA(row0, c + 1, (c + 1) & 1);
            } else {
                int ntile = tile + gridDim.x;
                if (ntile < NT) { stageA(ntile << 7, 0, 0); pf = true; }
                else issued = false;
            }
            if (issued) { CP_WAIT(1); } else { CP_WAIT(0); }
            __syncthreads();

            const uint32_t ast = (uint32_t)((c & 1)) * ABYTES;
#pragma unroll
            for (int ks = 0; ks < KC / 16; ks++) {
                const int k0 = ks * 16;
                const int kg = c * KC + k0;

                uint32_t af[MF][4];
#pragma unroll
                for (int mf = 0; mf < MF; mf++) {
                    uint32_t ao = (uint32_t)((wr0 + mf * 16 + a_row_l) * SA
                                             + k0 + a_kadd) * 2;
                    LDSM_X4(af[mf][0], af[mf][1], af[mf][2], af[mf][3],
                            aB + ast + ao);
                }
                uint32_t bh[NFRAG][2], bl[NFRAG][2];
#pragma unroll
                for (int nfp = 0; nfp < NFRAG / 2; nfp++) {
                    uint32_t bo = (uint32_t)((n0 + nfp * 16 + b_row_l) * SB
                                             + kg + b_kadd) * 2;
                    LDSM_X4(bh[2 * nfp][0], bh[2 * nfp][1],
                            bh[2 * nfp + 1][0], bh[2 * nfp + 1][1], whB + bo);
                    LDSM_X4(bl[2 * nfp][0], bl[2 * nfp][1],
                            bl[2 * nfp + 1][0], bl[2 * nfp + 1][1], wlB + bo);
                }
#pragma unroll
                for (int nf = 0; nf < NFRAG; nf++)
#pragma unroll
                    for (int mf = 0; mf < MF; mf++) {
                        MMA_F16(acc[mf][nf], af[mf], bh[nf]);
                        MMA_F16(acc[mf][nf], af[mf], bl[nf]);
                    }
            }
            __syncthreads();   // all reads done before next stage overwrites
        }

        // --- epilogue: bias (+relu), fp16 plane and/or fp32 stores ---
#pragma unroll
        for (int mf = 0; mf < MF; mf++) {
#pragma unroll
            for (int nf = 0; nf < NFRAG; nf++) {
                int col = n0 + nf * 8 + 2 * tq;
                int r = row0 + wr0 + mf * 16 + g;
                float b0 = __ldg(&bias[col]);
                float b1 = __ldg(&bias[col + 1]);
                float v[2][2] = {{acc[mf][nf][0] + b0, acc[mf][nf][1] + b1},
                                 {acc[mf][nf][2] + b0, acc[mf][nf][3] + b1}};
#pragma unroll
                for (int hrow = 0; hrow < 2; hrow++) {
                    int rr = r + hrow * 8;
                    if (rr >= M) continue;
                    float v0 = v[hrow][0], v1 = v[hrow][1];
                    if (RELU) { v0 = fmaxf(v0, 0.f); v1 = fmaxf(v1, 0.f); }
                    long long o = (long long)rr * NTILE + col;
                    if (WF16)
                        *(__half2*)(out16 + o) = __floats2half2_rn(v0, v1);
                    if (WF32)
                        *(float2*)(outF + o) = make_float2(v0, v1);
                }
            }
        }
    }
}

// ---------------- launch ------------------------------------------------------
extern "C" void kernel_launch(void* const* d_in, const int* in_sizes, int n_in,
                              void* d_out, int out_size) {
    (void)in_sizes; (void)n_in; (void)out_size;
    const float* features = (const float*)d_in[0];
    const int*   src      = (const int*)  d_in[1];
    const int*   dst      = (const int*)  d_in[2];
    const float* W_self1  = (const float*)d_in[3];
    const float* W_neigh1 = (const float*)d_in[4];
    const float* b1       = (const float*)d_in[5];
    const float* W_self2  = (const float*)d_in[6];
    const float* W_neigh2 = (const float*)d_in[7];
    const float* b2       = (const float*)d_in[8];
    const float* W_out    = (const float*)d_in[9];
    const float* b_out    = (const float*)d_in[10];
    float*       out      = (float*)d_out;

    __half *f16, *g16, *h1, *h2;
    cudaGetSymbolAddress((void**)&f16, g_f16);
    cudaGetSymbolAddress((void**)&g16, g_g16);
    cudaGetSymbolAddress((void**)&h1,  g_h1);
    cudaGetSymbolAddress((void**)&h2,  g_h2);

    // smem: 2 W planes [NTILE][KTOT+8] fp16 + 2 A stages [128][72] fp16
    const int SMEM_L = (2 * 128 * (256 + 8) + 2 * 128 * 72) * 2;  // 172032
    const int SMEM_O = (2 * 64  * (128 + 8) + 2 * 128 * 72) * 2;  //  71680
    cudaFuncSetAttribute(mma_gemm<256, 128, true, true, true, false>,
                         cudaFuncAttributeMaxDynamicSharedMemorySize, SMEM_L);
    cudaFuncSetAttribute(mma_gemm<128, 64, false, false, false, true>,
                         cudaFuncAttributeMaxDynamicSharedMemorySize, SMEM_O);

    const int EB = (N_EDGES + 255) / 256;          // 6250
    const int NB = (N_NODES + 255) / 256;          // 391
    const int GB = (N_NODES * 32 + 255) / 256;     // 12500 (warp per node)
    const int CB = (N_NODES * DIM / 4 + 255) / 256;
    const int PG = 148;

    // 1-4) feature fp16 plane (+deg zeroing) + CSR build
    prep_kernel<<<CB, 256>>>(features, N_NODES * DIM / 4);
    count_deg_kernel<<<EB, 256>>>(dst);
    scanoff_kernel<<<NB, 256>>>();
    build_csr_kernel<<<EB, 256>>>(src, dst);

    // 5-6) layer 1: gather(features) + dual GEMM -> h1 (fp16 plane)
    gather_mean_f16_kernel<<<GB, 256>>>(f16);
    mma_gemm<256, 128, true, true, true, false><<<PG, 512, SMEM_L>>>(
        f16, g16, W_self1, W_neigh1, b1, h1, nullptr, N_NODES);

    // 7-8) layer 2: gather(h1) + dual GEMM -> h2 (fp16 plane)
    gather_mean_f16_kernel<<<GB, 256>>>(h1);
    mma_gemm<256, 128, true, true, true, false><<<PG, 512, SMEM_L>>>(
        h1, g16, W_self2, W_neigh2, b2, h2, nullptr, N_NODES);

    // 9) output projection -> fp32 d_out
    mma_gemm<128, 64, false, false, false, true><<<PG, 512, SMEM_O>>>(
        h2, nullptr, W_out, nullptr, b_out, nullptr, out, N_NODES);
}